// round 3
// baseline (speedup 1.0000x reference)
#include <cuda_runtime.h>

// ---------------------------------------------------------------------------
// EfficientViT attention block.
//   K1: QKV = BN(W_{q,k,v} @ x)       (fused GEMM, BN epilogue)        [fp32]
//   K2: O   = softmax(Q K^T) V        (flash-attn, packed f32x2 FMA)
//   K3: out = BN(W_p @ relu(O))       (GEMM, relu on load, BN epilogue)[fp32]
// ---------------------------------------------------------------------------

namespace {
constexpr int BATCH = 2;
constexpr int CIN   = 384;
constexpr int NPIX  = 3136;     // 56*56
constexpr int HEADS = 8;
constexpr int KD    = 16;
constexpr int DV    = 64;
constexpr int DH    = 512;
constexpr int OCOUT = 384;
constexpr int BH    = BATCH * HEADS;
constexpr int NT    = NPIX / 64;   // 49 tiles of 64 pixels
constexpr float EPSBN = 1e-5f;

// attention smem partition (floats), strides padded for bank behavior
constexpr int SQ2S = 132;                       // dup Q row stride
constexpr int SKS  = 68;                        // Kt row stride
constexpr int SVS  = 68;                        // V row stride
constexpr int SPS  = 130;                       // dup P row stride
constexpr int OFF_Q = 0;                        // [16][132] dup-q : 8448 B
constexpr int OFF_K = 16 * SQ2S;                // [16][68]        : 4352 B
constexpr int OFF_V = OFF_K + 16 * SKS;         // [64][68]        : 17408 B
constexpr int OFF_P = OFF_V + 64 * SVS;         // [64][130] dup-q : 33280 B
constexpr int SMEM_FLOATS = OFF_P + 64 * SPS;   // 15872 floats = 63488 B
}

// scratch (static device arrays: allocation-free per harness rules)
__device__ __align__(16) float g_Q[BH * NPIX * KD];   // (bh, n, kd)
__device__ __align__(16) float g_K[BH * NPIX * KD];   // (bh, n, kd)
__device__ __align__(16) float g_V[BH * NPIX * DV];   // (bh, n, d)
__device__ __align__(16) float g_O[BH * NPIX * DV];   // (bh, n, d)

// ---- packed f32x2 helpers (native FFMA2 path on sm_103a, PTX-only) --------
using u64 = unsigned long long;
__device__ __forceinline__ u64 fma2(u64 a, u64 b, u64 acc) {
    asm("fma.rn.f32x2 %0, %1, %2, %0;" : "+l"(acc) : "l"(a), "l"(b));
    return acc;
}
__device__ __forceinline__ u64 mul2(u64 a, u64 b) {
    u64 d; asm("mul.rn.f32x2 %0, %1, %2;" : "=l"(d) : "l"(a), "l"(b)); return d;
}
__device__ __forceinline__ u64 pk(float lo, float hi) {
    u64 d; asm("mov.b64 %0, {%1, %2};" : "=l"(d) : "f"(lo), "f"(hi)); return d;
}
__device__ __forceinline__ float2 upk(u64 v) {
    float2 r; asm("mov.b64 {%0, %1}, %2;" : "=f"(r.x), "=f"(r.y) : "l"(v)); return r;
}

// ---------------------------------------------------------------------------
// Kernel 1: fused QKV projection + folded BatchNorm.
// grid (49, 12, 2), block 256. Each block: 64 out-channels x 64 pixels.
// ---------------------------------------------------------------------------
__global__ __launch_bounds__(256, 3) void qkv_kernel(
    const float* __restrict__ x,
    const float* __restrict__ wq, const float* __restrict__ wk, const float* __restrict__ wv,
    const float* __restrict__ qg, const float* __restrict__ qb, const float* __restrict__ qm, const float* __restrict__ qv,
    const float* __restrict__ kg, const float* __restrict__ kb, const float* __restrict__ km, const float* __restrict__ kvv,
    const float* __restrict__ vg, const float* __restrict__ vb, const float* __restrict__ vm, const float* __restrict__ vvv)
{
    __shared__ __align__(16) float Ws[64][17];
    __shared__ __align__(16) float Xs[16][64];

    const int b   = blockIdx.z;
    const int oc0 = blockIdx.y * 64;
    const int n0  = blockIdx.x * 64;
    const int tid = threadIdx.x;
    const int tx  = tid & 15, ty = tid >> 4;

    const int wrow = tid >> 2, wseg = tid & 3;
    const int xc   = tid >> 4, xn = (tid & 15) * 4;

    const int oc_w = oc0 + wrow;
    const float* wptr = (oc_w < 128) ? (wq + oc_w * CIN)
                      : (oc_w < 256) ? (wk + (oc_w - 128) * CIN)
                                     : (wv + (oc_w - 256) * CIN);
    const float* xptr = x + (b * CIN + xc) * NPIX + n0 + xn;

    float acc[4][4] = {};

    for (int kc = 0; kc < CIN; kc += 16) {
        float4 w4 = *(const float4*)(wptr + kc + wseg * 4);
        float4 x4 = *(const float4*)(xptr + kc * NPIX);
        Ws[wrow][wseg*4+0] = w4.x; Ws[wrow][wseg*4+1] = w4.y;
        Ws[wrow][wseg*4+2] = w4.z; Ws[wrow][wseg*4+3] = w4.w;
        *(float4*)&Xs[xc][xn] = x4;
        __syncthreads();
        #pragma unroll
        for (int kk = 0; kk < 16; kk++) {
            const float a0 = Ws[ty*4+0][kk], a1 = Ws[ty*4+1][kk];
            const float a2 = Ws[ty*4+2][kk], a3 = Ws[ty*4+3][kk];
            const float4 bv = *(const float4*)&Xs[kk][tx*4];
            acc[0][0] = fmaf(a0, bv.x, acc[0][0]); acc[0][1] = fmaf(a0, bv.y, acc[0][1]);
            acc[0][2] = fmaf(a0, bv.z, acc[0][2]); acc[0][3] = fmaf(a0, bv.w, acc[0][3]);
            acc[1][0] = fmaf(a1, bv.x, acc[1][0]); acc[1][1] = fmaf(a1, bv.y, acc[1][1]);
            acc[1][2] = fmaf(a1, bv.z, acc[1][2]); acc[1][3] = fmaf(a1, bv.w, acc[1][3]);
            acc[2][0] = fmaf(a2, bv.x, acc[2][0]); acc[2][1] = fmaf(a2, bv.y, acc[2][1]);
            acc[2][2] = fmaf(a2, bv.z, acc[2][2]); acc[2][3] = fmaf(a2, bv.w, acc[2][3]);
            acc[3][0] = fmaf(a3, bv.x, acc[3][0]); acc[3][1] = fmaf(a3, bv.y, acc[3][1]);
            acc[3][2] = fmaf(a3, bv.z, acc[3][2]); acc[3][3] = fmaf(a3, bv.w, acc[3][3]);
        }
        __syncthreads();
    }

    const int rbase = oc0 + ty * 4;
    float sc[4], sh[4];
    if (oc0 < 128) {           // Q
        #pragma unroll
        for (int i = 0; i < 4; i++) {
            const int oc = rbase + i;
            const float r = rsqrtf(qv[oc] + EPSBN);
            sc[i] = qg[oc] * r; sh[i] = qb[oc] - qm[oc] * sc[i];
        }
        const int head = rbase >> 4, kdb = rbase & 15;
        float* base = g_Q + (b * HEADS + head) * NPIX * KD + kdb;
        #pragma unroll
        for (int j = 0; j < 4; j++) {
            const int n = n0 + tx * 4 + j;
            float4 v = make_float4(fmaf(acc[0][j], sc[0], sh[0]), fmaf(acc[1][j], sc[1], sh[1]),
                                   fmaf(acc[2][j], sc[2], sh[2]), fmaf(acc[3][j], sc[3], sh[3]));
            *(float4*)(base + n * KD) = v;
        }
    } else if (oc0 < 256) {    // K
        const int rb = rbase - 128;
        #pragma unroll
        for (int i = 0; i < 4; i++) {
            const int oc = rb + i;
            const float r = rsqrtf(kvv[oc] + EPSBN);
            sc[i] = kg[oc] * r; sh[i] = kb[oc] - km[oc] * sc[i];
        }
        const int head = rb >> 4, kdb = rb & 15;
        float* base = g_K + (b * HEADS + head) * NPIX * KD + kdb;
        #pragma unroll
        for (int j = 0; j < 4; j++) {
            const int n = n0 + tx * 4 + j;
            float4 v = make_float4(fmaf(acc[0][j], sc[0], sh[0]), fmaf(acc[1][j], sc[1], sh[1]),
                                   fmaf(acc[2][j], sc[2], sh[2]), fmaf(acc[3][j], sc[3], sh[3]));
            *(float4*)(base + n * KD) = v;
        }
    } else {                   // V
        const int rb = rbase - 256;
        #pragma unroll
        for (int i = 0; i < 4; i++) {
            const int oc = rb + i;
            const float r = rsqrtf(vvv[oc] + EPSBN);
            sc[i] = vg[oc] * r; sh[i] = vb[oc] - vm[oc] * sc[i];
        }
        const int head = rb >> 6, db = rb & 63;
        float* base = g_V + (b * HEADS + head) * NPIX * DV + db;
        #pragma unroll
        for (int j = 0; j < 4; j++) {
            const int n = n0 + tx * 4 + j;
            float4 v = make_float4(fmaf(acc[0][j], sc[0], sh[0]), fmaf(acc[1][j], sc[1], sh[1]),
                                   fmaf(acc[2][j], sc[2], sh[2]), fmaf(acc[3][j], sc[3], sh[3]));
            *(float4*)(base + n * DV) = v;
        }
    }
}

// ---------------------------------------------------------------------------
// Kernel 2: flash attention with packed f32x2 FMA.  grid (49, 16), block 256.
// Thread (tx,ty): queries 4ty..4ty+3; keys/dims 4tx..4tx+3.
// QK^T: S packed over key pairs; Q stored duplicated -> LDS.64 gives (q,q).
// P.V : O packed over dim pairs; P stored duplicated -> LDS.64 gives (p,p).
// Dynamic smem 63488 B.
// ---------------------------------------------------------------------------
__global__ __launch_bounds__(256, 3) void attn_kernel()
{
    extern __shared__ __align__(16) float sm[];
    float* sQ2 = sm + OFF_Q;   // [16][SQ2S]  sQ2[kk][2q]   = sQ2[kk][2q+1] = Q[q][kk]
    float* sK  = sm + OFF_K;   // [16][SKS]   sK[kk][k]     = K[k][kk]
    float* sV  = sm + OFF_V;   // [64][SVS]   sV[k][d]      = V[k][d]
    float* sP  = sm + OFF_P;   // [64][SPS]   sP[k][2q]     = sP[k][2q+1] = P[q][k]

    const int bh  = blockIdx.y;
    const int q0  = blockIdx.x * 64;
    const int tid = threadIdx.x, tx = tid & 15, ty = tid >> 4;
    const int lrow = tid >> 2, lseg = tid & 3;

    {   // load + transpose + duplicate Q tile (once)
        float4 q4 = *(const float4*)(g_Q + (bh * NPIX + q0 + lrow) * KD + lseg * 4);
        *(u64*)&sQ2[(lseg*4+0)*SQ2S + 2*lrow] = pk(q4.x, q4.x);
        *(u64*)&sQ2[(lseg*4+1)*SQ2S + 2*lrow] = pk(q4.y, q4.y);
        *(u64*)&sQ2[(lseg*4+2)*SQ2S + 2*lrow] = pk(q4.z, q4.z);
        *(u64*)&sQ2[(lseg*4+3)*SQ2S + 2*lrow] = pk(q4.w, q4.w);
    }

    float m_i[4], l_i[4];
    u64 o2[4][2] = {};           // (O[q_i][4tx+2jp], O[q_i][4tx+2jp+1])
    #pragma unroll
    for (int i = 0; i < 4; i++) { m_i[i] = -1e30f; l_i[i] = 0.f; }

    for (int kt = 0; kt < NT; kt++) {
        const int k0 = kt * 64;
        {   // load + transpose K tile
            float4 k4 = *(const float4*)(g_K + (bh * NPIX + k0 + lrow) * KD + lseg * 4);
            sK[(lseg*4+0)*SKS + lrow] = k4.x;
            sK[(lseg*4+1)*SKS + lrow] = k4.y;
            sK[(lseg*4+2)*SKS + lrow] = k4.z;
            sK[(lseg*4+3)*SKS + lrow] = k4.w;
        }
        {   // load V tile
            const float* vp = g_V + (bh * NPIX + k0) * DV;
            #pragma unroll
            for (int r = 0; r < 4; r++) {
                const int idx = tid + 256 * r;
                const int row = idx >> 4, seg = (idx & 15) * 4;
                *(float4*)&sV[row * SVS + seg] = *(const float4*)(vp + row * DV + seg);
            }
        }
        __syncthreads();

        // ---- S = Q K^T : 8 packed FMAs per kk ----
        u64 s2[4][2] = {};
        #pragma unroll
        for (int kk = 0; kk < 16; kk++) {
            const float* qrow = &sQ2[kk * SQ2S + 8 * ty];
            const u64 a0 = *(const u64*)(qrow + 0);
            const u64 a1 = *(const u64*)(qrow + 2);
            const u64 a2 = *(const u64*)(qrow + 4);
            const u64 a3 = *(const u64*)(qrow + 6);
            const ulonglong2 bb = *(const ulonglong2*)&sK[kk * SKS + 4 * tx];
            s2[0][0] = fma2(a0, bb.x, s2[0][0]); s2[0][1] = fma2(a0, bb.y, s2[0][1]);
            s2[1][0] = fma2(a1, bb.x, s2[1][0]); s2[1][1] = fma2(a1, bb.y, s2[1][1]);
            s2[2][0] = fma2(a2, bb.x, s2[2][0]); s2[2][1] = fma2(a2, bb.y, s2[2][1]);
            s2[3][0] = fma2(a3, bb.x, s2[3][0]); s2[3][1] = fma2(a3, bb.y, s2[3][1]);
        }

        // ---- online softmax per query row; write duplicated P ----
        #pragma unroll
        for (int i = 0; i < 4; i++) {
            const float2 u0 = upk(s2[i][0]);
            const float2 u1 = upk(s2[i][1]);
            float sv0 = u0.x, sv1 = u0.y, sv2 = u1.x, sv3 = u1.y;
            float mt = fmaxf(fmaxf(sv0, sv1), fmaxf(sv2, sv3));
            #pragma unroll
            for (int off = 8; off >= 1; off >>= 1)
                mt = fmaxf(mt, __shfl_xor_sync(0xffffffffu, mt, off));
            const float mn   = fmaxf(m_i[i], mt);
            const float corr = __expf(m_i[i] - mn);
            m_i[i] = mn;
            const float e0 = __expf(sv0 - mn), e1 = __expf(sv1 - mn);
            const float e2 = __expf(sv2 - mn), e3 = __expf(sv3 - mn);
            float rs = (e0 + e1) + (e2 + e3);
            #pragma unroll
            for (int off = 8; off >= 1; off >>= 1)
                rs += __shfl_xor_sync(0xffffffffu, rs, off);
            l_i[i] = l_i[i] * corr + rs;
            const u64 c2 = pk(corr, corr);
            o2[i][0] = mul2(o2[i][0], c2);
            o2[i][1] = mul2(o2[i][1], c2);
            float* prow = &sP[2 * (4 * ty + i)];
            *(u64*)(prow + (4*tx+0) * SPS) = pk(e0, e0);
            *(u64*)(prow + (4*tx+1) * SPS) = pk(e1, e1);
            *(u64*)(prow + (4*tx+2) * SPS) = pk(e2, e2);
            *(u64*)(prow + (4*tx+3) * SPS) = pk(e3, e3);
        }
        __syncthreads();

        // ---- O += P @ V : 8 packed FMAs per kk ----
        #pragma unroll 4
        for (int kk = 0; kk < 64; kk++) {
            const float* prow = &sP[kk * SPS + 8 * ty];
            const u64 p0 = *(const u64*)(prow + 0);
            const u64 p1 = *(const u64*)(prow + 2);
            const u64 p2 = *(const u64*)(prow + 4);
            const u64 p3 = *(const u64*)(prow + 6);
            const ulonglong2 vv = *(const ulonglong2*)&sV[kk * SVS + 4 * tx];
            o2[0][0] = fma2(p0, vv.x, o2[0][0]); o2[0][1] = fma2(p0, vv.y, o2[0][1]);
            o2[1][0] = fma2(p1, vv.x, o2[1][0]); o2[1][1] = fma2(p1, vv.y, o2[1][1]);
            o2[2][0] = fma2(p2, vv.x, o2[2][0]); o2[2][1] = fma2(p2, vv.y, o2[2][1]);
            o2[3][0] = fma2(p3, vv.x, o2[3][0]); o2[3][1] = fma2(p3, vv.y, o2[3][1]);
        }
        __syncthreads();
    }

    #pragma unroll
    for (int i = 0; i < 4; i++) {
        const float inv = 1.f / l_i[i];
        const float2 a = upk(o2[i][0]);
        const float2 b = upk(o2[i][1]);
        float4 v = make_float4(a.x * inv, a.y * inv, b.x * inv, b.y * inv);
        *(float4*)(g_O + (bh * NPIX + q0 + 4*ty + i) * DV + 4*tx) = v;
    }
}

// ---------------------------------------------------------------------------
// Kernel 3: out = BN(W_p @ relu(O)). grid (49, 6, 2), block 256.
// ---------------------------------------------------------------------------
__global__ __launch_bounds__(256, 3) void proj_kernel(
    const float* __restrict__ wp, const float* __restrict__ pg, const float* __restrict__ pb,
    const float* __restrict__ pm, const float* __restrict__ pvv, float* __restrict__ out)
{
    __shared__ float Ws[64][17];
    __shared__ __align__(16) float Xs[16][64];

    const int b   = blockIdx.z;
    const int oc0 = blockIdx.y * 64;
    const int n0  = blockIdx.x * 64;
    const int tid = threadIdx.x, tx = tid & 15, ty = tid >> 4;
    const int wrow = tid >> 2, wseg = tid & 3;
    const int xn   = tid >> 2, xseg = tid & 3;

    float acc[4][4] = {};

    for (int kc = 0; kc < DH; kc += 16) {
        float4 w4 = *(const float4*)(wp + (oc0 + wrow) * DH + kc + wseg * 4);
        const int head = kc >> 6, db = kc & 63;
        float4 x4 = *(const float4*)(g_O + ((b * HEADS + head) * NPIX + n0 + xn) * DV + db + xseg * 4);
        x4.x = fmaxf(x4.x, 0.f); x4.y = fmaxf(x4.y, 0.f);
        x4.z = fmaxf(x4.z, 0.f); x4.w = fmaxf(x4.w, 0.f);
        Ws[wrow][wseg*4+0] = w4.x; Ws[wrow][wseg*4+1] = w4.y;
        Ws[wrow][wseg*4+2] = w4.z; Ws[wrow][wseg*4+3] = w4.w;
        Xs[xseg*4+0][xn] = x4.x; Xs[xseg*4+1][xn] = x4.y;
        Xs[xseg*4+2][xn] = x4.z; Xs[xseg*4+3][xn] = x4.w;
        __syncthreads();
        #pragma unroll
        for (int kk = 0; kk < 16; kk++) {
            const float a0 = Ws[ty*4+0][kk], a1 = Ws[ty*4+1][kk];
            const float a2 = Ws[ty*4+2][kk], a3 = Ws[ty*4+3][kk];
            const float4 bv = *(const float4*)&Xs[kk][tx*4];
            acc[0][0] = fmaf(a0, bv.x, acc[0][0]); acc[0][1] = fmaf(a0, bv.y, acc[0][1]);
            acc[0][2] = fmaf(a0, bv.z, acc[0][2]); acc[0][3] = fmaf(a0, bv.w, acc[0][3]);
            acc[1][0] = fmaf(a1, bv.x, acc[1][0]); acc[1][1] = fmaf(a1, bv.y, acc[1][1]);
            acc[1][2] = fmaf(a1, bv.z, acc[1][2]); acc[1][3] = fmaf(a1, bv.w, acc[1][3]);
            acc[2][0] = fmaf(a2, bv.x, acc[2][0]); acc[2][1] = fmaf(a2, bv.y, acc[2][1]);
            acc[2][2] = fmaf(a2, bv.z, acc[2][2]); acc[2][3] = fmaf(a2, bv.w, acc[2][3]);
            acc[3][0] = fmaf(a3, bv.x, acc[3][0]); acc[3][1] = fmaf(a3, bv.y, acc[3][1]);
            acc[3][2] = fmaf(a3, bv.z, acc[3][2]); acc[3][3] = fmaf(a3, bv.w, acc[3][3]);
        }
        __syncthreads();
    }

    #pragma unroll
    for (int i = 0; i < 4; i++) {
        const int oc = oc0 + ty * 4 + i;
        const float r  = rsqrtf(pvv[oc] + EPSBN);
        const float sc = pg[oc] * r;
        const float sh = pb[oc] - pm[oc] * sc;
        float4 v = make_float4(fmaf(acc[i][0], sc, sh), fmaf(acc[i][1], sc, sh),
                               fmaf(acc[i][2], sc, sh), fmaf(acc[i][3], sc, sh));
        *(float4*)(out + (b * OCOUT + oc) * NPIX + n0 + tx * 4) = v;
    }
}

// ---------------------------------------------------------------------------
extern "C" void kernel_launch(void* const* d_in, const int* in_sizes, int n_in,
                              void* d_out, int out_size)
{
    (void)in_sizes; (void)n_in; (void)out_size;
    const float* x   = (const float*)d_in[0];
    const float* wq  = (const float*)d_in[1];
    const float* qg  = (const float*)d_in[2];
    const float* qb  = (const float*)d_in[3];
    const float* qm  = (const float*)d_in[4];
    const float* qv  = (const float*)d_in[5];
    const float* wk  = (const float*)d_in[6];
    const float* kg  = (const float*)d_in[7];
    const float* kb  = (const float*)d_in[8];
    const float* km  = (const float*)d_in[9];
    const float* kvv = (const float*)d_in[10];
    const float* wv  = (const float*)d_in[11];
    const float* vg  = (const float*)d_in[12];
    const float* vb  = (const float*)d_in[13];
    const float* vm  = (const float*)d_in[14];
    const float* vvv = (const float*)d_in[15];
    const float* wp  = (const float*)d_in[16];
    const float* pg  = (const float*)d_in[17];
    const float* pb  = (const float*)d_in[18];
    const float* pm  = (const float*)d_in[19];
    const float* pvv = (const float*)d_in[20];
    float* out = (float*)d_out;

    const int attn_smem = SMEM_FLOATS * (int)sizeof(float);   // 63488 B
    cudaFuncSetAttribute(attn_kernel, cudaFuncAttributeMaxDynamicSharedMemorySize, attn_smem);

    dim3 blk(256);
    qkv_kernel<<<dim3(NT, 12, BATCH), blk>>>(x, wq, wk, wv,
                                             qg, qb, qm, qv,
                                             kg, kb, km, kvv,
                                             vg, vb, vm, vvv);
    attn_kernel<<<dim3(NT, BH), blk, attn_smem>>>();
    proj_kernel<<<dim3(NT, 6, BATCH), blk>>>(wp, pg, pb, pm, pvv, out);
}

// round 5
// speedup vs baseline: 2.0852x; 2.0852x over previous
#include <cuda_runtime.h>
#include <cuda_bf16.h>
#include <cstdint>

// ---------------------------------------------------------------------------
// EfficientViT attention block.
//   K1: QKV = BN(W @ x)   fp32 GEMM; epilogue splits to bf16 hi/lo pairs:
//                         Qp/Kp (bh,n,kdpair) interleaved {hi,lo},
//                         Vp transposed (bh,d,keypair) interleaved {hi,lo}
//   K2: O = softmax(QK^T)V   mma.sync bf16 m16n8k16, split-bf16 3-MMA
//                            products, no max-subtraction, f32 accum
//   K3: out = BN(Wp @ relu(O))   fp32 GEMM
// ---------------------------------------------------------------------------

namespace {
constexpr int BATCH = 2;
constexpr int CIN   = 384;
constexpr int NPIX  = 3136;     // 56*56
constexpr int HEADS = 8;
constexpr int KD    = 16;
constexpr int DV    = 64;
constexpr int DH    = 512;
constexpr int OCOUT = 384;
constexpr int BH    = BATCH * HEADS;
constexpr int NT64  = NPIX / 64;   // 49 tiles of 64
constexpr float EPSBN = 1e-5f;
}

// scratch (static device arrays: allocation-free per harness rules)
// Qp/Kp: per (bh, pixel): 8 uint2, one per kd-pair -> {bf16x2 hi, bf16x2 lo}
__device__ __align__(16) uint2 g_Qp[BH * NPIX * (KD / 2)];
__device__ __align__(16) uint2 g_Kp[BH * NPIX * (KD / 2)];
// Vp: per (bh, d): NPIX/2 uint2, one per key-pair -> {hi, lo}
__device__ __align__(16) uint2 g_Vp[BH * DV * (NPIX / 2)];
__device__ __align__(16) float g_O[BH * NPIX * DV];   // (bh, n, d)

// split fp32 pair -> bf16x2 hi (v0 in low half) + bf16x2 lo (residuals)
__device__ __forceinline__ void split2(float v0, float v1, uint32_t& hi, uint32_t& lo) {
    __nv_bfloat16 b0 = __float2bfloat16(v0), b1 = __float2bfloat16(v1);
    hi = ((uint32_t)__bfloat16_as_ushort(b1) << 16) | (uint32_t)__bfloat16_as_ushort(b0);
    float r0 = v0 - __bfloat162float(b0);
    float r1 = v1 - __bfloat162float(b1);
    asm("cvt.rn.bf16x2.f32 %0, %1, %2;" : "=r"(lo) : "f"(r1), "f"(r0));
}

// mma.sync m16n8k16 bf16 (baseline PTX ISA, legal on plain sm_103)
__device__ __forceinline__ void mma16816(float* c, const uint32_t* a, uint32_t b0, uint32_t b1) {
    asm volatile("mma.sync.aligned.m16n8k16.row.col.f32.bf16.bf16.f32 "
        "{%0,%1,%2,%3}, {%4,%5,%6,%7}, {%8,%9}, {%0,%1,%2,%3};"
        : "+f"(c[0]), "+f"(c[1]), "+f"(c[2]), "+f"(c[3])
        : "r"(a[0]), "r"(a[1]), "r"(a[2]), "r"(a[3]), "r"(b0), "r"(b1));
}

// ---------------------------------------------------------------------------
// Kernel 1: fused QKV projection + folded BatchNorm + bf16 hi/lo split.
// grid (49, 12, 2), block 256. 64 out-channels x 64 pixels per block.
// ---------------------------------------------------------------------------
__global__ __launch_bounds__(256, 3) void qkv_kernel(
    const float* __restrict__ x,
    const float* __restrict__ wq, const float* __restrict__ wk, const float* __restrict__ wv,
    const float* __restrict__ qg, const float* __restrict__ qb, const float* __restrict__ qm, const float* __restrict__ qv,
    const float* __restrict__ kg, const float* __restrict__ kb, const float* __restrict__ km, const float* __restrict__ kvv,
    const float* __restrict__ vg, const float* __restrict__ vb, const float* __restrict__ vm, const float* __restrict__ vvv)
{
    __shared__ __align__(16) float Ws[64][17];
    __shared__ __align__(16) float Xs[16][64];

    const int b   = blockIdx.z;
    const int oc0 = blockIdx.y * 64;
    const int n0  = blockIdx.x * 64;
    const int tid = threadIdx.x;
    const int tx  = tid & 15, ty = tid >> 4;

    const int wrow = tid >> 2, wseg = tid & 3;
    const int xc   = tid >> 4, xn = (tid & 15) * 4;

    const int oc_w = oc0 + wrow;
    const float* wptr = (oc_w < 128) ? (wq + oc_w * CIN)
                      : (oc_w < 256) ? (wk + (oc_w - 128) * CIN)
                                     : (wv + (oc_w - 256) * CIN);
    const float* xptr = x + (b * CIN + xc) * NPIX + n0 + xn;

    float acc[4][4] = {};

    for (int kc = 0; kc < CIN; kc += 16) {
        float4 w4 = *(const float4*)(wptr + kc + wseg * 4);
        float4 x4 = *(const float4*)(xptr + kc * NPIX);
        Ws[wrow][wseg*4+0] = w4.x; Ws[wrow][wseg*4+1] = w4.y;
        Ws[wrow][wseg*4+2] = w4.z; Ws[wrow][wseg*4+3] = w4.w;
        *(float4*)&Xs[xc][xn] = x4;
        __syncthreads();
        #pragma unroll
        for (int kk = 0; kk < 16; kk++) {
            const float a0 = Ws[ty*4+0][kk], a1 = Ws[ty*4+1][kk];
            const float a2 = Ws[ty*4+2][kk], a3 = Ws[ty*4+3][kk];
            const float4 bv = *(const float4*)&Xs[kk][tx*4];
            acc[0][0] = fmaf(a0, bv.x, acc[0][0]); acc[0][1] = fmaf(a0, bv.y, acc[0][1]);
            acc[0][2] = fmaf(a0, bv.z, acc[0][2]); acc[0][3] = fmaf(a0, bv.w, acc[0][3]);
            acc[1][0] = fmaf(a1, bv.x, acc[1][0]); acc[1][1] = fmaf(a1, bv.y, acc[1][1]);
            acc[1][2] = fmaf(a1, bv.z, acc[1][2]); acc[1][3] = fmaf(a1, bv.w, acc[1][3]);
            acc[2][0] = fmaf(a2, bv.x, acc[2][0]); acc[2][1] = fmaf(a2, bv.y, acc[2][1]);
            acc[2][2] = fmaf(a2, bv.z, acc[2][2]); acc[2][3] = fmaf(a2, bv.w, acc[2][3]);
            acc[3][0] = fmaf(a3, bv.x, acc[3][0]); acc[3][1] = fmaf(a3, bv.y, acc[3][1]);
            acc[3][2] = fmaf(a3, bv.z, acc[3][2]); acc[3][3] = fmaf(a3, bv.w, acc[3][3]);
        }
        __syncthreads();
    }

    const int rbase = oc0 + ty * 4;
    float sc[4], sh[4];
    if (oc0 < 256) {           // Q or K: pack along kd pairs
        const bool isQ = (oc0 < 128);
        const int rb = isQ ? rbase : (rbase - 128);
        const float* gg = isQ ? qg : kg;  const float* bb = isQ ? qb : kb;
        const float* mm = isQ ? qm : km;  const float* vv = isQ ? qv : kvv;
        #pragma unroll
        for (int i = 0; i < 4; i++) {
            const int oc = rb + i;
            const float r = rsqrtf(vv[oc] + EPSBN);
            sc[i] = gg[oc] * r; sh[i] = bb[oc] - mm[oc] * sc[i];
        }
        const int head = rb >> 4, kdb = rb & 15;     // kdb in {0,4,8,12}
        uint2* base = (isQ ? g_Qp : g_Kp) + (size_t)(b * HEADS + head) * NPIX * 8 + (kdb >> 1);
        #pragma unroll
        for (int j = 0; j < 4; j++) {
            const int n = n0 + tx * 4 + j;
            const float v0 = fmaf(acc[0][j], sc[0], sh[0]);
            const float v1 = fmaf(acc[1][j], sc[1], sh[1]);
            const float v2 = fmaf(acc[2][j], sc[2], sh[2]);
            const float v3 = fmaf(acc[3][j], sc[3], sh[3]);
            uint32_t h01, l01, h23, l23;
            split2(v0, v1, h01, l01);
            split2(v2, v3, h23, l23);
            *(uint4*)(base + (size_t)n * 8) = make_uint4(h01, l01, h23, l23);
        }
    } else {                   // V: transpose to (bh, d, keypair), pack along pixels
        const int rb = rbase - 256;
        #pragma unroll
        for (int i = 0; i < 4; i++) {
            const int oc = rb + i;
            const float r = rsqrtf(vvv[oc] + EPSBN);
            sc[i] = vg[oc] * r; sh[i] = vb[oc] - vm[oc] * sc[i];
        }
        const int head = rb >> 6, db = rb & 63;
        const int bh = b * HEADS + head;
        #pragma unroll
        for (int i = 0; i < 4; i++) {
            const float v0 = fmaf(acc[i][0], sc[i], sh[i]);
            const float v1 = fmaf(acc[i][1], sc[i], sh[i]);
            const float v2 = fmaf(acc[i][2], sc[i], sh[i]);
            const float v3 = fmaf(acc[i][3], sc[i], sh[i]);
            uint32_t h01, l01, h23, l23;
            split2(v0, v1, h01, l01);
            split2(v2, v3, h23, l23);
            uint2* dst = g_Vp + (size_t)(bh * DV + db + i) * (NPIX / 2) + ((n0 + tx * 4) >> 1);
            *(uint4*)dst = make_uint4(h01, l01, h23, l23);
        }
    }
}

// ---------------------------------------------------------------------------
// Kernel 2: attention via mma.sync bf16. grid (49, 16), block 128 (4 warps).
// Warp w owns 16 queries (rows q0+16w .. +15). Key tiles of 64.
// No max-subtraction (|logit| << 80): exp directly, rowsum in registers.
// Split-bf16: S = QhKh + QhKl + QlKh;  O += PhVh + PlVh + PhVl.
// QK^T accumulator fragments are directly A-operand compatible for PV.
// ---------------------------------------------------------------------------
__global__ __launch_bounds__(128) void attn_mma_kernel()
{
    const int bh  = blockIdx.y;
    const int q0  = blockIdx.x * 64;
    const int tid = threadIdx.x;
    const int w   = tid >> 5, lane = tid & 31;
    const int g   = lane >> 2, t = lane & 3;
    const int row0 = q0 + w * 16 + g;          // second row = row0 + 8

    // ---- Q fragments (hi/lo), loaded once ----
    const uint2* Qp = g_Qp + (size_t)bh * NPIX * 8;
    const uint2 qa0 = Qp[(size_t)row0 * 8 + t];
    const uint2 qa1 = Qp[(size_t)(row0 + 8) * 8 + t];
    const uint2 qa2 = Qp[(size_t)row0 * 8 + t + 4];
    const uint2 qa3 = Qp[(size_t)(row0 + 8) * 8 + t + 4];
    const uint32_t Qhi[4] = {qa0.x, qa1.x, qa2.x, qa3.x};
    const uint32_t Qlo[4] = {qa0.y, qa1.y, qa2.y, qa3.y};

    const uint2* Kp = g_Kp + (size_t)bh * NPIX * 8;
    const uint2* Vp = g_Vp + (size_t)bh * DV * (NPIX / 2);

    float o[8][4] = {};
    float rs0 = 0.f, rs1 = 0.f;

    for (int kt = 0; kt < NT64; kt++) {
        const int k0 = kt * 64;

        // ---- S = Q K^T : 8 key-groups x 3 split MMAs ----
        float s[8][4] = {};
        #pragma unroll
        for (int j = 0; j < 8; j++) {
            const uint2* kb = Kp + (size_t)(k0 + 8 * j + g) * 8;
            const uint2 b0 = kb[t];
            const uint2 b1 = kb[t + 4];
            mma16816(s[j], Qhi, b0.x, b1.x);   // Qh*Kh
            mma16816(s[j], Qhi, b0.y, b1.y);   // Qh*Kl
            mma16816(s[j], Qlo, b0.x, b1.x);   // Ql*Kh
        }

        // ---- exp + rowsum partials ----
        #pragma unroll
        for (int j = 0; j < 8; j++) {
            s[j][0] = __expf(fminf(s[j][0], 80.f));
            s[j][1] = __expf(fminf(s[j][1], 80.f));
            s[j][2] = __expf(fminf(s[j][2], 80.f));
            s[j][3] = __expf(fminf(s[j][3], 80.f));
            rs0 += s[j][0] + s[j][1];
            rs1 += s[j][2] + s[j][3];
        }

        // ---- O += P V : 4 k-steps x 8 d-groups x 3 split MMAs ----
        #pragma unroll
        for (int ss = 0; ss < 4; ss++) {
            uint32_t ph[4], pl[4];
            split2(s[2*ss  ][0], s[2*ss  ][1], ph[0], pl[0]);
            split2(s[2*ss  ][2], s[2*ss  ][3], ph[1], pl[1]);
            split2(s[2*ss+1][0], s[2*ss+1][1], ph[2], pl[2]);
            split2(s[2*ss+1][2], s[2*ss+1][3], ph[3], pl[3]);
            const int kp0 = (k0 >> 1) + 8 * ss + t;
            #pragma unroll
            for (int j = 0; j < 8; j++) {
                const uint2* vb = Vp + (size_t)(8 * j + g) * (NPIX / 2) + kp0;
                const uint2 b0 = vb[0];
                const uint2 b1 = vb[4];
                mma16816(o[j], ph, b0.x, b1.x);   // Ph*Vh
                mma16816(o[j], pl, b0.x, b1.x);   // Pl*Vh
                mma16816(o[j], ph, b0.y, b1.y);   // Ph*Vl
            }
        }
    }

    // ---- finalize rowsums (reduce over the 4 lanes of each row group) ----
    rs0 += __shfl_xor_sync(0xffffffffu, rs0, 1);
    rs0 += __shfl_xor_sync(0xffffffffu, rs0, 2);
    rs1 += __shfl_xor_sync(0xffffffffu, rs1, 1);
    rs1 += __shfl_xor_sync(0xffffffffu, rs1, 2);
    const float inv0 = 1.f / rs0;
    const float inv1 = 1.f / rs1;

    // ---- store O ----
    float* op0 = g_O + ((size_t)bh * NPIX + row0) * DV;
    float* op1 = op0 + 8 * DV;
    #pragma unroll
    for (int j = 0; j < 8; j++) {
        const int d = 8 * j + 2 * t;
        *(float2*)(op0 + d) = make_float2(o[j][0] * inv0, o[j][1] * inv0);
        *(float2*)(op1 + d) = make_float2(o[j][2] * inv1, o[j][3] * inv1);
    }
}

// ---------------------------------------------------------------------------
// Kernel 3: out = BN(W_p @ relu(O)). grid (49, 6, 2), block 256.
// ---------------------------------------------------------------------------
__global__ __launch_bounds__(256, 3) void proj_kernel(
    const float* __restrict__ wp, const float* __restrict__ pg, const float* __restrict__ pb,
    const float* __restrict__ pm, const float* __restrict__ pvv, float* __restrict__ out)
{
    __shared__ float Ws[64][17];
    __shared__ __align__(16) float Xs[16][64];

    const int b   = blockIdx.z;
    const int oc0 = blockIdx.y * 64;
    const int n0  = blockIdx.x * 64;
    const int tid = threadIdx.x, tx = tid & 15, ty = tid >> 4;
    const int wrow = tid >> 2, wseg = tid & 3;
    const int xn   = tid >> 2, xseg = tid & 3;

    float acc[4][4] = {};

    for (int kc = 0; kc < DH; kc += 16) {
        float4 w4 = *(const float4*)(wp + (oc0 + wrow) * DH + kc + wseg * 4);
        const int head = kc >> 6, db = kc & 63;
        float4 x4 = *(const float4*)(g_O + ((size_t)(b * HEADS + head) * NPIX + n0 + xn) * DV + db + xseg * 4);
        x4.x = fmaxf(x4.x, 0.f); x4.y = fmaxf(x4.y, 0.f);
        x4.z = fmaxf(x4.z, 0.f); x4.w = fmaxf(x4.w, 0.f);
        Ws[wrow][wseg*4+0] = w4.x; Ws[wrow][wseg*4+1] = w4.y;
        Ws[wrow][wseg*4+2] = w4.z; Ws[wrow][wseg*4+3] = w4.w;
        Xs[xseg*4+0][xn] = x4.x; Xs[xseg*4+1][xn] = x4.y;
        Xs[xseg*4+2][xn] = x4.z; Xs[xseg*4+3][xn] = x4.w;
        __syncthreads();
        #pragma unroll
        for (int kk = 0; kk < 16; kk++) {
            const float a0 = Ws[ty*4+0][kk], a1 = Ws[ty*4+1][kk];
            const float a2 = Ws[ty*4+2][kk], a3 = Ws[ty*4+3][kk];
            const float4 bv = *(const float4*)&Xs[kk][tx*4];
            acc[0][0] = fmaf(a0, bv.x, acc[0][0]); acc[0][1] = fmaf(a0, bv.y, acc[0][1]);
            acc[0][2] = fmaf(a0, bv.z, acc[0][2]); acc[0][3] = fmaf(a0, bv.w, acc[0][3]);
            acc[1][0] = fmaf(a1, bv.x, acc[1][0]); acc[1][1] = fmaf(a1, bv.y, acc[1][1]);
            acc[1][2] = fmaf(a1, bv.z, acc[1][2]); acc[1][3] = fmaf(a1, bv.w, acc[1][3]);
            acc[2][0] = fmaf(a2, bv.x, acc[2][0]); acc[2][1] = fmaf(a2, bv.y, acc[2][1]);
            acc[2][2] = fmaf(a2, bv.z, acc[2][2]); acc[2][3] = fmaf(a2, bv.w, acc[2][3]);
            acc[3][0] = fmaf(a3, bv.x, acc[3][0]); acc[3][1] = fmaf(a3, bv.y, acc[3][1]);
            acc[3][2] = fmaf(a3, bv.z, acc[3][2]); acc[3][3] = fmaf(a3, bv.w, acc[3][3]);
        }
        __syncthreads();
    }

    #pragma unroll
    for (int i = 0; i < 4; i++) {
        const int oc = oc0 + ty * 4 + i;
        const float r  = rsqrtf(pvv[oc] + EPSBN);
        const float sc = pg[oc] * r;
        const float sh = pb[oc] - pm[oc] * sc;
        float4 v = make_float4(fmaf(acc[i][0], sc, sh), fmaf(acc[i][1], sc, sh),
                               fmaf(acc[i][2], sc, sh), fmaf(acc[i][3], sc, sh));
        *(float4*)(out + (size_t)(b * OCOUT + oc) * NPIX + n0 + tx * 4) = v;
    }
}

// ---------------------------------------------------------------------------
extern "C" void kernel_launch(void* const* d_in, const int* in_sizes, int n_in,
                              void* d_out, int out_size)
{
    (void)in_sizes; (void)n_in; (void)out_size;
    const float* x   = (const float*)d_in[0];
    const float* wq  = (const float*)d_in[1];
    const float* qg  = (const float*)d_in[2];
    const float* qb  = (const float*)d_in[3];
    const float* qm  = (const float*)d_in[4];
    const float* qv  = (const float*)d_in[5];
    const float* wk  = (const float*)d_in[6];
    const float* kg  = (const float*)d_in[7];
    const float* kb  = (const float*)d_in[8];
    const float* km  = (const float*)d_in[9];
    const float* kvv = (const float*)d_in[10];
    const float* wv  = (const float*)d_in[11];
    const float* vg  = (const float*)d_in[12];
    const float* vb  = (const float*)d_in[13];
    const float* vm  = (const float*)d_in[14];
    const float* vvv = (const float*)d_in[15];
    const float* wp  = (const float*)d_in[16];
    const float* pg  = (const float*)d_in[17];
    const float* pb  = (const float*)d_in[18];
    const float* pm  = (const float*)d_in[19];
    const float* pvv = (const float*)d_in[20];
    float* out = (float*)d_out;

    dim3 blk(256);
    qkv_kernel<<<dim3(NT64, 12, BATCH), blk>>>(x, wq, wk, wv,
                                               qg, qb, qm, qv,
                                               kg, kb, km, kvv,
                                               vg, vb, vm, vvv);
    attn_mma_kernel<<<dim3(NT64, BH), dim3(128)>>>();
    proj_kernel<<<dim3(NT64, 6, BATCH), blk>>>(wp, pg, pb, pm, pvv, out);
}

// round 6
// speedup vs baseline: 3.0698x; 1.4722x over previous
#include <cuda_runtime.h>
#include <cuda_fp16.h>
#include <cstdint>

// ---------------------------------------------------------------------------
// EfficientViT attention block.
//   K1: QKV = BN(W @ x)   fp32 GEMM; epilogue: Q/K split fp16 hi/lo pairs,
//                         V transposed (bh,d,keypair) single fp16
//   K2: O = softmax(QK^T)V   mma.sync m16n8k16 fp16: QK = 3-MMA split,
//                            PV = 1 MMA (P,V fp16), online max, smem-staged K/V
//   K3: out = BN(Wp @ relu(O))   fp32 GEMM
// ---------------------------------------------------------------------------

namespace {
constexpr int BATCH = 2;
constexpr int CIN   = 384;
constexpr int NPIX  = 3136;     // 56*56
constexpr int HEADS = 8;
constexpr int KD    = 16;
constexpr int DV    = 64;
constexpr int DH    = 512;
constexpr int OCOUT = 384;
constexpr int BH    = BATCH * HEADS;
constexpr int NT64  = NPIX / 64;             // 49 key tiles
constexpr int QT128 = (NPIX + 127) / 128;    // 25 q tiles (last partial)
constexpr float EPSBN = 1e-5f;
}

// scratch (static device arrays: allocation-free per harness rules)
// Qp/Kp: per (bh, pixel): 8 uint2, one per kd-pair -> {f16x2 hi, f16x2 lo}
__device__ __align__(16) uint2 g_Qp[BH * NPIX * (KD / 2)];
__device__ __align__(16) uint2 g_Kp[BH * NPIX * (KD / 2)];
// Vh: per (bh, d): NPIX/2 uints, one per key-pair -> f16x2
__device__ __align__(16) uint32_t g_Vh[BH * DV * (NPIX / 2)];
__device__ __align__(16) float g_O[BH * NPIX * DV];   // (bh, n, d)

// split fp32 pair -> f16x2 hi (v0 low half) + f16x2 lo (residuals)
__device__ __forceinline__ void split2h(float v0, float v1, uint32_t& hi, uint32_t& lo) {
    __half h0 = __float2half_rn(v0), h1 = __float2half_rn(v1);
    hi = ((uint32_t)__half_as_ushort(h1) << 16) | (uint32_t)__half_as_ushort(h0);
    float r0 = v0 - __half2float(h0);
    float r1 = v1 - __half2float(h1);
    asm("cvt.rn.f16x2.f32 %0, %1, %2;" : "=r"(lo) : "f"(r1), "f"(r0));
}
__device__ __forceinline__ uint32_t packh(float v0, float v1) {
    uint32_t d; asm("cvt.rn.f16x2.f32 %0, %1, %2;" : "=r"(d) : "f"(v1), "f"(v0)); return d;
}

// mma.sync m16n8k16 fp16 -> f32 accum (baseline PTX, legal on sm_103)
__device__ __forceinline__ void mma16816h(float* c, const uint32_t* a, uint32_t b0, uint32_t b1) {
    asm volatile("mma.sync.aligned.m16n8k16.row.col.f32.f16.f16.f32 "
        "{%0,%1,%2,%3}, {%4,%5,%6,%7}, {%8,%9}, {%0,%1,%2,%3};"
        : "+f"(c[0]), "+f"(c[1]), "+f"(c[2]), "+f"(c[3])
        : "r"(a[0]), "r"(a[1]), "r"(a[2]), "r"(a[3]), "r"(b0), "r"(b1));
}

// ---------------------------------------------------------------------------
// Kernel 1: fused QKV projection + folded BatchNorm + fp16 pack epilogues.
// grid (49, 12, 2), block 256. 64 out-channels x 64 pixels per block.
// ---------------------------------------------------------------------------
__global__ __launch_bounds__(256, 3) void qkv_kernel(
    const float* __restrict__ x,
    const float* __restrict__ wq, const float* __restrict__ wk, const float* __restrict__ wv,
    const float* __restrict__ qg, const float* __restrict__ qb, const float* __restrict__ qm, const float* __restrict__ qv,
    const float* __restrict__ kg, const float* __restrict__ kb, const float* __restrict__ km, const float* __restrict__ kvv,
    const float* __restrict__ vg, const float* __restrict__ vb, const float* __restrict__ vm, const float* __restrict__ vvv)
{
    __shared__ __align__(16) float Ws[64][17];
    __shared__ __align__(16) float Xs[16][64];

    const int b   = blockIdx.z;
    const int oc0 = blockIdx.y * 64;
    const int n0  = blockIdx.x * 64;
    const int tid = threadIdx.x;
    const int tx  = tid & 15, ty = tid >> 4;

    const int wrow = tid >> 2, wseg = tid & 3;
    const int xc   = tid >> 4, xn = (tid & 15) * 4;

    const int oc_w = oc0 + wrow;
    const float* wptr = (oc_w < 128) ? (wq + oc_w * CIN)
                      : (oc_w < 256) ? (wk + (oc_w - 128) * CIN)
                                     : (wv + (oc_w - 256) * CIN);
    const float* xptr = x + (b * CIN + xc) * NPIX + n0 + xn;

    float acc[4][4] = {};

    for (int kc = 0; kc < CIN; kc += 16) {
        float4 w4 = *(const float4*)(wptr + kc + wseg * 4);
        float4 x4 = *(const float4*)(xptr + kc * NPIX);
        Ws[wrow][wseg*4+0] = w4.x; Ws[wrow][wseg*4+1] = w4.y;
        Ws[wrow][wseg*4+2] = w4.z; Ws[wrow][wseg*4+3] = w4.w;
        *(float4*)&Xs[xc][xn] = x4;
        __syncthreads();
        #pragma unroll
        for (int kk = 0; kk < 16; kk++) {
            const float a0 = Ws[ty*4+0][kk], a1 = Ws[ty*4+1][kk];
            const float a2 = Ws[ty*4+2][kk], a3 = Ws[ty*4+3][kk];
            const float4 bv = *(const float4*)&Xs[kk][tx*4];
            acc[0][0] = fmaf(a0, bv.x, acc[0][0]); acc[0][1] = fmaf(a0, bv.y, acc[0][1]);
            acc[0][2] = fmaf(a0, bv.z, acc[0][2]); acc[0][3] = fmaf(a0, bv.w, acc[0][3]);
            acc[1][0] = fmaf(a1, bv.x, acc[1][0]); acc[1][1] = fmaf(a1, bv.y, acc[1][1]);
            acc[1][2] = fmaf(a1, bv.z, acc[1][2]); acc[1][3] = fmaf(a1, bv.w, acc[1][3]);
            acc[2][0] = fmaf(a2, bv.x, acc[2][0]); acc[2][1] = fmaf(a2, bv.y, acc[2][1]);
            acc[2][2] = fmaf(a2, bv.z, acc[2][2]); acc[2][3] = fmaf(a2, bv.w, acc[2][3]);
            acc[3][0] = fmaf(a3, bv.x, acc[3][0]); acc[3][1] = fmaf(a3, bv.y, acc[3][1]);
            acc[3][2] = fmaf(a3, bv.z, acc[3][2]); acc[3][3] = fmaf(a3, bv.w, acc[3][3]);
        }
        __syncthreads();
    }

    const int rbase = oc0 + ty * 4;
    float sc[4], sh[4];
    if (oc0 < 256) {           // Q or K: pack along kd pairs (fp16 hi/lo)
        const bool isQ = (oc0 < 128);
        const int rb = isQ ? rbase : (rbase - 128);
        const float* gg = isQ ? qg : kg;  const float* bb = isQ ? qb : kb;
        const float* mm = isQ ? qm : km;  const float* vv = isQ ? qv : kvv;
        #pragma unroll
        for (int i = 0; i < 4; i++) {
            const int oc = rb + i;
            const float r = rsqrtf(vv[oc] + EPSBN);
            sc[i] = gg[oc] * r; sh[i] = bb[oc] - mm[oc] * sc[i];
        }
        const int head = rb >> 4, kdb = rb & 15;     // kdb in {0,4,8,12}
        uint2* base = (isQ ? g_Qp : g_Kp) + (size_t)(b * HEADS + head) * NPIX * 8 + (kdb >> 1);
        #pragma unroll
        for (int j = 0; j < 4; j++) {
            const int n = n0 + tx * 4 + j;
            const float v0 = fmaf(acc[0][j], sc[0], sh[0]);
            const float v1 = fmaf(acc[1][j], sc[1], sh[1]);
            const float v2 = fmaf(acc[2][j], sc[2], sh[2]);
            const float v3 = fmaf(acc[3][j], sc[3], sh[3]);
            uint32_t h01, l01, h23, l23;
            split2h(v0, v1, h01, l01);
            split2h(v2, v3, h23, l23);
            *(uint4*)(base + (size_t)n * 8) = make_uint4(h01, l01, h23, l23);
        }
    } else {                   // V: transpose to (bh, d, keypair), single fp16
        const int rb = rbase - 256;
        #pragma unroll
        for (int i = 0; i < 4; i++) {
            const int oc = rb + i;
            const float r = rsqrtf(vvv[oc] + EPSBN);
            sc[i] = vg[oc] * r; sh[i] = vb[oc] - vm[oc] * sc[i];
        }
        const int head = rb >> 6, db = rb & 63;
        const int bh = b * HEADS + head;
        #pragma unroll
        for (int i = 0; i < 4; i++) {
            const float v0 = fmaf(acc[i][0], sc[i], sh[i]);
            const float v1 = fmaf(acc[i][1], sc[i], sh[i]);
            const float v2 = fmaf(acc[i][2], sc[i], sh[i]);
            const float v3 = fmaf(acc[i][3], sc[i], sh[i]);
            uint32_t* dst = g_Vh + (size_t)(bh * DV + db + i) * (NPIX / 2) + ((n0 + tx * 4) >> 1);
            *(uint2*)dst = make_uint2(packh(v0, v1), packh(v2, v3));
        }
    }
}

// ---------------------------------------------------------------------------
// Kernel 2: attention via fp16 mma.sync with online max.
// grid (25, 16), block 256 (8 warps). Warp w owns 16 queries of a 128-q tile.
// K/V key-tiles of 64 staged in smem (shared by all 8 warps).
// QK^T: 3 split MMAs (hi/lo fp16). PV: 1 MMA (P,V fp16). f32 accumulators.
// ---------------------------------------------------------------------------
__global__ __launch_bounds__(256) void attn_mma_kernel()
{
    __shared__ __align__(16) uint2    sK[64][9];    // [key][kd-pair {hi,lo}], pad 9
    __shared__ __align__(16) uint32_t sV[64][34];   // [d][keypair f16x2], pad 34

    const int bh  = blockIdx.y;
    const int q0  = blockIdx.x * 128;
    const int tid = threadIdx.x;
    const int w   = tid >> 5, lane = tid & 31;
    const int g   = lane >> 2, t = lane & 3;
    const int row0 = q0 + w * 16 + g;          // second row = row0 + 8

    // ---- Q fragments (hi/lo), loaded once (clamped for tail tile) ----
    const uint2* Qp = g_Qp + (size_t)bh * NPIX * 8;
    const int r0c = min(row0, NPIX - 1), r1c = min(row0 + 8, NPIX - 1);
    const uint2 qa0 = Qp[(size_t)r0c * 8 + t];
    const uint2 qa1 = Qp[(size_t)r1c * 8 + t];
    const uint2 qa2 = Qp[(size_t)r0c * 8 + t + 4];
    const uint2 qa3 = Qp[(size_t)r1c * 8 + t + 4];
    const uint32_t Qhi[4] = {qa0.x, qa1.x, qa2.x, qa3.x};
    const uint32_t Qlo[4] = {qa0.y, qa1.y, qa2.y, qa3.y};

    const uint2*    Kp = g_Kp + (size_t)bh * NPIX * 8;
    const uint32_t* Vp = g_Vh + (size_t)bh * DV * (NPIX / 2);

    float o[8][4] = {};
    float rs0 = 0.f, rs1 = 0.f;
    float m0 = -3.0e38f, m1 = -3.0e38f;

    // staging indices
    const int skey = tid >> 2, scol = (tid & 3) * 2;   // K: 64 keys x 4 loaders
    const int sd   = tid >> 2, svc  = (tid & 3) * 8;   // V: 64 d x 4 loaders

    for (int kt = 0; kt < NT64; kt++) {
        const int k0 = kt * 64;

        __syncthreads();   // previous tile fully consumed
        {   // stage K tile: 64 keys x 8 uint2
            uint4 kv = *(const uint4*)(Kp + (size_t)(k0 + skey) * 8 + scol);
            sK[skey][scol]     = make_uint2(kv.x, kv.y);
            sK[skey][scol + 1] = make_uint2(kv.z, kv.w);
        }
        {   // stage V tile: 64 d x 32 f16x2
            const uint32_t* vgp = Vp + (size_t)sd * (NPIX / 2) + (k0 >> 1) + svc;
            uint4 a = *(const uint4*)vgp;
            uint4 b = *(const uint4*)(vgp + 4);
            *(uint2*)&sV[sd][svc]     = make_uint2(a.x, a.y);
            *(uint2*)&sV[sd][svc + 2] = make_uint2(a.z, a.w);
            *(uint2*)&sV[sd][svc + 4] = make_uint2(b.x, b.y);
            *(uint2*)&sV[sd][svc + 6] = make_uint2(b.z, b.w);
        }
        __syncthreads();   // tile ready

        // ---- S = Q K^T : 8 key-groups x 3 split MMAs ----
        float s[8][4] = {};
        #pragma unroll
        for (int j = 0; j < 8; j++) {
            const uint2 b0 = sK[8 * j + g][t];
            const uint2 b1 = sK[8 * j + g][t + 4];
            mma16816h(s[j], Qhi, b0.x, b1.x);   // Qh*Kh
            mma16816h(s[j], Qhi, b0.y, b1.y);   // Qh*Kl
            mma16816h(s[j], Qlo, b0.x, b1.x);   // Ql*Kh
        }

        // ---- online max update ----
        float mt0 = s[0][0], mt1 = s[0][2];
        #pragma unroll
        for (int j = 0; j < 8; j++) {
            mt0 = fmaxf(mt0, fmaxf(s[j][0], s[j][1]));
            mt1 = fmaxf(mt1, fmaxf(s[j][2], s[j][3]));
        }
        mt0 = fmaxf(mt0, __shfl_xor_sync(0xffffffffu, mt0, 1));
        mt0 = fmaxf(mt0, __shfl_xor_sync(0xffffffffu, mt0, 2));
        mt1 = fmaxf(mt1, __shfl_xor_sync(0xffffffffu, mt1, 1));
        mt1 = fmaxf(mt1, __shfl_xor_sync(0xffffffffu, mt1, 2));
        const float mn0 = fmaxf(m0, mt0), mn1 = fmaxf(m1, mt1);
        const float c0 = __expf(m0 - mn0), c1 = __expf(m1 - mn1);
        m0 = mn0; m1 = mn1;
        rs0 *= c0; rs1 *= c1;
        #pragma unroll
        for (int j = 0; j < 8; j++) {
            o[j][0] *= c0; o[j][1] *= c0;
            o[j][2] *= c1; o[j][3] *= c1;
        }

        // ---- P = exp(S - m), rowsum, fp16 pack ----
        #pragma unroll
        for (int j = 0; j < 8; j++) {
            s[j][0] = __expf(s[j][0] - mn0);
            s[j][1] = __expf(s[j][1] - mn0);
            s[j][2] = __expf(s[j][2] - mn1);
            s[j][3] = __expf(s[j][3] - mn1);
            rs0 += s[j][0] + s[j][1];
            rs1 += s[j][2] + s[j][3];
        }

        // ---- O += P V : 4 k-steps x 8 d-groups x 1 MMA ----
        #pragma unroll
        for (int ss = 0; ss < 4; ss++) {
            uint32_t ph[4];
            ph[0] = packh(s[2*ss  ][0], s[2*ss  ][1]);
            ph[1] = packh(s[2*ss  ][2], s[2*ss  ][3]);
            ph[2] = packh(s[2*ss+1][0], s[2*ss+1][1]);
            ph[3] = packh(s[2*ss+1][2], s[2*ss+1][3]);
            const int col = 8 * ss + t;
            #pragma unroll
            for (int j = 0; j < 8; j++) {
                const uint32_t b0 = sV[8 * j + g][col];
                const uint32_t b1 = sV[8 * j + g][col + 4];
                mma16816h(o[j], ph, b0, b1);
            }
        }
    }

    // ---- finalize rowsums (reduce over the 4 lanes of each row group) ----
    rs0 += __shfl_xor_sync(0xffffffffu, rs0, 1);
    rs0 += __shfl_xor_sync(0xffffffffu, rs0, 2);
    rs1 += __shfl_xor_sync(0xffffffffu, rs1, 1);
    rs1 += __shfl_xor_sync(0xffffffffu, rs1, 2);
    const float inv0 = 1.f / rs0;
    const float inv1 = 1.f / rs1;

    // ---- store O ----
    if (row0 < NPIX) {
        float* op0 = g_O + ((size_t)bh * NPIX + row0) * DV;
        #pragma unroll
        for (int j = 0; j < 8; j++) {
            const int d = 8 * j + 2 * t;
            *(float2*)(op0 + d) = make_float2(o[j][0] * inv0, o[j][1] * inv0);
        }
        if (row0 + 8 < NPIX) {
            float* op1 = op0 + 8 * DV;
            #pragma unroll
            for (int j = 0; j < 8; j++) {
                const int d = 8 * j + 2 * t;
                *(float2*)(op1 + d) = make_float2(o[j][2] * inv1, o[j][3] * inv1);
            }
        }
    }
}

// ---------------------------------------------------------------------------
// Kernel 3: out = BN(W_p @ relu(O)). grid (49, 6, 2), block 256.
// ---------------------------------------------------------------------------
__global__ __launch_bounds__(256, 3) void proj_kernel(
    const float* __restrict__ wp, const float* __restrict__ pg, const float* __restrict__ pb,
    const float* __restrict__ pm, const float* __restrict__ pvv, float* __restrict__ out)
{
    __shared__ float Ws[64][17];
    __shared__ __align__(16) float Xs[16][64];

    const int b   = blockIdx.z;
    const int oc0 = blockIdx.y * 64;
    const int n0  = blockIdx.x * 64;
    const int tid = threadIdx.x, tx = tid & 15, ty = tid >> 4;
    const int wrow = tid >> 2, wseg = tid & 3;
    const int xn   = tid >> 2, xseg = tid & 3;

    float acc[4][4] = {};

    for (int kc = 0; kc < DH; kc += 16) {
        float4 w4 = *(const float4*)(wp + (oc0 + wrow) * DH + kc + wseg * 4);
        const int head = kc >> 6, db = kc & 63;
        float4 x4 = *(const float4*)(g_O + ((size_t)(b * HEADS + head) * NPIX + n0 + xn) * DV + db + xseg * 4);
        x4.x = fmaxf(x4.x, 0.f); x4.y = fmaxf(x4.y, 0.f);
        x4.z = fmaxf(x4.z, 0.f); x4.w = fmaxf(x4.w, 0.f);
        Ws[wrow][wseg*4+0] = w4.x; Ws[wrow][wseg*4+1] = w4.y;
        Ws[wrow][wseg*4+2] = w4.z; Ws[wrow][wseg*4+3] = w4.w;
        Xs[xseg*4+0][xn] = x4.x; Xs[xseg*4+1][xn] = x4.y;
        Xs[xseg*4+2][xn] = x4.z; Xs[xseg*4+3][xn] = x4.w;
        __syncthreads();
        #pragma unroll
        for (int kk = 0; kk < 16; kk++) {
            const float a0 = Ws[ty*4+0][kk], a1 = Ws[ty*4+1][kk];
            const float a2 = Ws[ty*4+2][kk], a3 = Ws[ty*4+3][kk];
            const float4 bv = *(const float4*)&Xs[kk][tx*4];
            acc[0][0] = fmaf(a0, bv.x, acc[0][0]); acc[0][1] = fmaf(a0, bv.y, acc[0][1]);
            acc[0][2] = fmaf(a0, bv.z, acc[0][2]); acc[0][3] = fmaf(a0, bv.w, acc[0][3]);
            acc[1][0] = fmaf(a1, bv.x, acc[1][0]); acc[1][1] = fmaf(a1, bv.y, acc[1][1]);
            acc[1][2] = fmaf(a1, bv.z, acc[1][2]); acc[1][3] = fmaf(a1, bv.w, acc[1][3]);
            acc[2][0] = fmaf(a2, bv.x, acc[2][0]); acc[2][1] = fmaf(a2, bv.y, acc[2][1]);
            acc[2][2] = fmaf(a2, bv.z, acc[2][2]); acc[2][3] = fmaf(a2, bv.w, acc[2][3]);
            acc[3][0] = fmaf(a3, bv.x, acc[3][0]); acc[3][1] = fmaf(a3, bv.y, acc[3][1]);
            acc[3][2] = fmaf(a3, bv.z, acc[3][2]); acc[3][3] = fmaf(a3, bv.w, acc[3][3]);
        }
        __syncthreads();
    }

    #pragma unroll
    for (int i = 0; i < 4; i++) {
        const int oc = oc0 + ty * 4 + i;
        const float r  = rsqrtf(pvv[oc] + EPSBN);
        const float sc = pg[oc] * r;
        const float sh = pb[oc] - pm[oc] * sc;
        float4 v = make_float4(fmaf(acc[i][0], sc, sh), fmaf(acc[i][1], sc, sh),
                               fmaf(acc[i][2], sc, sh), fmaf(acc[i][3], sc, sh));
        *(float4*)(out + (size_t)(b * OCOUT + oc) * NPIX + n0 + tx * 4) = v;
    }
}

// ---------------------------------------------------------------------------
extern "C" void kernel_launch(void* const* d_in, const int* in_sizes, int n_in,
                              void* d_out, int out_size)
{
    (void)in_sizes; (void)n_in; (void)out_size;
    const float* x   = (const float*)d_in[0];
    const float* wq  = (const float*)d_in[1];
    const float* qg  = (const float*)d_in[2];
    const float* qb  = (const float*)d_in[3];
    const float* qm  = (const float*)d_in[4];
    const float* qv  = (const float*)d_in[5];
    const float* wk  = (const float*)d_in[6];
    const float* kg  = (const float*)d_in[7];
    const float* kb  = (const float*)d_in[8];
    const float* km  = (const float*)d_in[9];
    const float* kvv = (const float*)d_in[10];
    const float* wv  = (const float*)d_in[11];
    const float* vg  = (const float*)d_in[12];
    const float* vb  = (const float*)d_in[13];
    const float* vm  = (const float*)d_in[14];
    const float* vvv = (const float*)d_in[15];
    const float* wp  = (const float*)d_in[16];
    const float* pg  = (const float*)d_in[17];
    const float* pb  = (const float*)d_in[18];
    const float* pm  = (const float*)d_in[19];
    const float* pvv = (const float*)d_in[20];
    float* out = (float*)d_out;

    dim3 blk(256);
    qkv_kernel<<<dim3(NT64, 12, BATCH), blk>>>(x, wq, wk, wv,
                                               qg, qb, qm, qv,
                                               kg, kb, km, kvv,
                                               vg, vb, vm, vvv);
    attn_mma_kernel<<<dim3(QT128, BH), dim3(256)>>>();
    proj_kernel<<<dim3(NT64, 6, BATCH), blk>>>(wp, pg, pb, pm, pvv, out);
}

// round 7
// speedup vs baseline: 3.6950x; 1.2037x over previous
#include <cuda_runtime.h>
#include <cuda_fp16.h>
#include <cstdint>

// ---------------------------------------------------------------------------
// EfficientViT attention block — all three GEMMs on tensor cores (mma.sync
// m16n8k16 fp16), fp32-accuracy via hi/lo split operands (3-MMA products).
//   P1: prep_x  : x -> transposed fp16 hi/lo pairs  g_Xp[b][pix][icpair]
//   P2: prep_w  : BN-scale-folded, split weights g_Wall (qkv) / g_Wpp (proj)
//   K1: qkv_mma : Q/K (split pairs) + V (transposed fp16) via MMA
//   K2: attn    : softmax(QK^T)V, online max; writes relu(O) split pairs
//   K3: proj_mma: out = Wp @ relu(O) + shift via MMA
// ---------------------------------------------------------------------------

namespace {
constexpr int BATCH = 2;
constexpr int CIN   = 384;
constexpr int NPIX  = 3136;     // 56*56
constexpr int HEADS = 8;
constexpr int KD    = 16;
constexpr int DV    = 64;
constexpr int DH    = 512;
constexpr int OCOUT = 384;
constexpr int BH    = BATCH * HEADS;
constexpr int NT64  = NPIX / 64;             // 49 key tiles
constexpr int QT128 = (NPIX + 127) / 128;    // 25 pixel tiles of 128
constexpr int ICP   = CIN / 2;               // 192 ic-pairs
constexpr int DHP   = DH / 2;                // 256 ic-pairs for proj
constexpr float EPSBN = 1e-5f;
}

// scratch (static device arrays: allocation-free per harness rules)
__device__ __align__(16) uint2    g_Xp[BATCH * NPIX * ICP];        // x^T split
__device__ __align__(16) uint2    g_Wall[(256 + DH) * ICP];        // 768 rows q,k,v
__device__ __align__(16) uint2    g_Wpp[OCOUT * DHP];              // proj W
__device__            float       g_shiftAll[768];
__device__            float       g_shiftP[OCOUT];
__device__ __align__(16) uint2    g_Qp[BH * NPIX * 8];             // [bh][pix][kdpair]{hi,lo}
__device__ __align__(16) uint2    g_Kp[BH * NPIX * 8];
__device__ __align__(16) uint32_t g_Vh[BH * DV * (NPIX / 2)];      // [bh][d][pixpair] f16x2
__device__ __align__(16) uint2    g_Oph[BH * NPIX * (DV / 2)];     // relu(O) split [bh][pix][dpair]

// split fp32 pair -> f16x2 hi (v0 low half) + f16x2 lo (residuals)
__device__ __forceinline__ void split2h(float v0, float v1, uint32_t& hi, uint32_t& lo) {
    __half h0 = __float2half_rn(v0), h1 = __float2half_rn(v1);
    hi = ((uint32_t)__half_as_ushort(h1) << 16) | (uint32_t)__half_as_ushort(h0);
    float r0 = v0 - __half2float(h0);
    float r1 = v1 - __half2float(h1);
    asm("cvt.rn.f16x2.f32 %0, %1, %2;" : "=r"(lo) : "f"(r1), "f"(r0));
}
__device__ __forceinline__ uint32_t packh(float v0, float v1) {
    uint32_t d; asm("cvt.rn.f16x2.f32 %0, %1, %2;" : "=r"(d) : "f"(v1), "f"(v0)); return d;
}

// mma.sync m16n8k16 fp16 -> f32 accum
// A frag: {(g,t),(g+8,t),(g,t+4),(g+8,t+4)} pair-granularity; B: n=g, kpair=t/t+4;
// C: row=g/g+8, col=2t/2t+1.   (empirically validated in rounds 5-6)
__device__ __forceinline__ void mma16816h(float* c, const uint32_t* a, uint32_t b0, uint32_t b1) {
    asm volatile("mma.sync.aligned.m16n8k16.row.col.f32.f16.f16.f32 "
        "{%0,%1,%2,%3}, {%4,%5,%6,%7}, {%8,%9}, {%0,%1,%2,%3};"
        : "+f"(c[0]), "+f"(c[1]), "+f"(c[2]), "+f"(c[3])
        : "r"(a[0]), "r"(a[1]), "r"(a[2]), "r"(a[3]), "r"(b0), "r"(b1));
}

// ---------------------------------------------------------------------------
// P1: transpose + split x. grid (49, 6, 2), block 256. 64 pix x 64 ch per blk.
// ---------------------------------------------------------------------------
__global__ __launch_bounds__(256) void prep_x(const float* __restrict__ x)
{
    __shared__ float s[8][66];
    const int pix0 = blockIdx.x * 64;
    const int cc0  = blockIdx.y * 64;
    const int b    = blockIdx.z;
    const int tid  = threadIdx.x;
    const int lr = tid >> 5, lc = (tid & 31) * 2;
    const int pix = tid >> 2, gp = tid & 3;

    for (int cc = cc0; cc < cc0 + 64; cc += 8) {
        float2 v = *(const float2*)(x + ((size_t)b * CIN + cc + lr) * NPIX + pix0 + lc);
        s[lr][lc] = v.x; s[lr][lc + 1] = v.y;
        __syncthreads();
        uint32_t hi, lo;
        split2h(s[2 * gp][pix], s[2 * gp + 1][pix], hi, lo);
        g_Xp[((size_t)b * NPIX + pix0 + pix) * ICP + (cc >> 1) + gp] = make_uint2(hi, lo);
        __syncthreads();
    }
}

// ---------------------------------------------------------------------------
// P2: fold BN scale into weights, split fp16 hi/lo; compute shifts.
// grid 1152, block 256. rows 0..767 -> g_Wall (q,k,v), 768..1151 -> g_Wpp.
// ---------------------------------------------------------------------------
__global__ __launch_bounds__(256) void prep_w(
    const float* __restrict__ wq, const float* __restrict__ wk,
    const float* __restrict__ wv, const float* __restrict__ wp,
    const float* __restrict__ qg, const float* __restrict__ qb, const float* __restrict__ qm, const float* __restrict__ qv,
    const float* __restrict__ kg, const float* __restrict__ kb, const float* __restrict__ km, const float* __restrict__ kvv,
    const float* __restrict__ vg, const float* __restrict__ vb, const float* __restrict__ vm, const float* __restrict__ vvv,
    const float* __restrict__ pg, const float* __restrict__ pb, const float* __restrict__ pm, const float* __restrict__ pvv)
{
    const int r = blockIdx.x, t = threadIdx.x;
    if (r < 768) {
        const float *w, *gg, *bb, *mm, *vx; int rr;
        if (r < 128)      { w = wq; gg = qg; bb = qb; mm = qm; vx = qv;  rr = r; }
        else if (r < 256) { w = wk; gg = kg; bb = kb; mm = km; vx = kvv; rr = r - 128; }
        else              { w = wv; gg = vg; bb = vb; mm = vm; vx = vvv; rr = r - 256; }
        const float sc = gg[rr] * rsqrtf(vx[rr] + EPSBN);
        if (t == 0) g_shiftAll[r] = bb[rr] - mm[rr] * sc;
        if (t < ICP) {
            float2 w2 = *(const float2*)(w + (size_t)rr * CIN + 2 * t);
            uint32_t hi, lo; split2h(w2.x * sc, w2.y * sc, hi, lo);
            g_Wall[(size_t)r * ICP + t] = make_uint2(hi, lo);
        }
    } else {
        const int rp = r - 768;
        const float sc = pg[rp] * rsqrtf(pvv[rp] + EPSBN);
        if (t == 0) g_shiftP[rp] = pb[rp] - pm[rp] * sc;
        float2 w2 = *(const float2*)(wp + (size_t)rp * DH + 2 * t);
        uint32_t hi, lo; split2h(w2.x * sc, w2.y * sc, hi, lo);
        g_Wpp[(size_t)rp * DHP + t] = make_uint2(hi, lo);
    }
}

// ---------------------------------------------------------------------------
// K1: QKV projection via MMA. grid (25, 6, 2), block 256 (8 warps).
// Block: 128 pixels (M) x 128 out-channels (N), K=384 in 24 steps.
// by: 0 -> Q(oc 0-127), 1 -> K, 2..5 -> V(oc 256-767).
// ---------------------------------------------------------------------------
__global__ __launch_bounds__(256, 2) void qkv_mma()
{
    __shared__ uint2 sW[128][9];

    const int by  = blockIdx.y, b = blockIdx.z;
    const int oc0 = by * 128;
    const int pix0 = blockIdx.x * 128;
    const int tid = threadIdx.x;
    const int w   = tid >> 5, lane = tid & 31;
    const int g   = lane >> 2, t = lane & 3;
    const int row0 = pix0 + 16 * w + g;
    const int r0c = min(row0, NPIX - 1), r1c = min(row0 + 8, NPIX - 1);

    const uint2* Xb0 = g_Xp + (size_t)b * NPIX * ICP + (size_t)r0c * ICP;
    const uint2* Xb1 = g_Xp + (size_t)b * NPIX * ICP + (size_t)r1c * ICP;

    float acc[16][4] = {};

    for (int s = 0; s < 24; s++) {
        __syncthreads();
        {   // stage 128 oc x 8 pairs of W
            const int i0 = tid * 4;
            #pragma unroll
            for (int i = 0; i < 4; i++) {
                const int idx = i0 + i, rr = idx >> 3, pp = idx & 7;
                sW[rr][pp] = g_Wall[(size_t)(oc0 + rr) * ICP + 8 * s + pp];
            }
        }
        __syncthreads();

        const uint2 a0 = Xb0[8 * s + t];
        const uint2 a1 = Xb1[8 * s + t];
        const uint2 a2 = Xb0[8 * s + t + 4];
        const uint2 a3 = Xb1[8 * s + t + 4];
        const uint32_t Ah[4] = {a0.x, a1.x, a2.x, a3.x};
        const uint32_t Al[4] = {a0.y, a1.y, a2.y, a3.y};

        #pragma unroll
        for (int j = 0; j < 16; j++) {
            const uint2 b0 = sW[8 * j + g][t];
            const uint2 b1 = sW[8 * j + g][t + 4];
            mma16816h(acc[j], Ah, b0.x, b1.x);
            mma16816h(acc[j], Ah, b0.y, b1.y);
            mma16816h(acc[j], Al, b0.x, b1.x);
        }
    }

    if (by < 2) {
        // ---- Q or K: kd-pairs are in-lane (cols 2t, 2t+1) ----
        uint2* QK = (by == 0) ? g_Qp : g_Kp;
        #pragma unroll
        for (int j = 0; j < 16; j++) {
            const int ocl = 8 * j + 2 * t;
            const float s0 = g_shiftAll[oc0 + ocl], s1 = g_shiftAll[oc0 + ocl + 1];
            const int head = ocl >> 4, kdp = (ocl & 15) >> 1;
            uint2* base = QK + ((size_t)(b * HEADS + head) * NPIX) * 8 + kdp;
            uint32_t hi, lo;
            if (row0 < NPIX) {
                split2h(acc[j][0] + s0, acc[j][1] + s1, hi, lo);
                base[(size_t)row0 * 8] = make_uint2(hi, lo);
            }
            if (row0 + 8 < NPIX) {
                split2h(acc[j][2] + s0, acc[j][3] + s1, hi, lo);
                base[(size_t)(row0 + 8) * 8] = make_uint2(hi, lo);
            }
        }
    } else {
        // ---- V: pixel-pairs via shfl (neighbor pixel = lane+4) ----
        #pragma unroll
        for (int j = 0; j < 16; j++) {
            const int ocv = (by - 2) * 128 + 8 * j + 2 * t;
            const float s0 = g_shiftAll[256 + ocv], s1 = g_shiftAll[256 + ocv + 1];
            const int head = ocv >> 6, d = ocv & 63;
            const float v00 = acc[j][0] + s0, v01 = acc[j][1] + s1;
            const float v10 = acc[j][2] + s0, v11 = acc[j][3] + s1;
            const float n00 = __shfl_down_sync(0xffffffffu, v00, 4);
            const float n01 = __shfl_down_sync(0xffffffffu, v01, 4);
            const float n10 = __shfl_down_sync(0xffffffffu, v10, 4);
            const float n11 = __shfl_down_sync(0xffffffffu, v11, 4);
            if (!(g & 1)) {
                uint32_t* vb = g_Vh + ((size_t)(b * HEADS + head) * DV + d) * (NPIX / 2);
                const int pp0 = row0 >> 1, pp1 = (row0 + 8) >> 1;
                if (row0 + 1 < NPIX) {
                    vb[pp0] = packh(v00, n00);
                    vb[(NPIX / 2) + pp0] = packh(v01, n01);
                }
                if (row0 + 9 < NPIX) {
                    vb[pp1] = packh(v10, n10);
                    vb[(NPIX / 2) + pp1] = packh(v11, n11);
                }
            }
        }
    }
}

// ---------------------------------------------------------------------------
// K2: attention via fp16 mma.sync with online max. grid (25, 16), block 256.
// Epilogue writes relu(O)/rowsum as fp16 hi/lo pairs to g_Oph.
// ---------------------------------------------------------------------------
__global__ __launch_bounds__(256) void attn_mma_kernel()
{
    __shared__ __align__(16) uint2    sK[64][9];    // [key][kd-pair {hi,lo}]
    __shared__ __align__(16) uint32_t sV[64][34];   // [d][keypair f16x2]

    const int bh  = blockIdx.y;
    const int q0  = blockIdx.x * 128;
    const int tid = threadIdx.x;
    const int w   = tid >> 5, lane = tid & 31;
    const int g   = lane >> 2, t = lane & 3;
    const int row0 = q0 + w * 16 + g;

    const uint2* Qp = g_Qp + (size_t)bh * NPIX * 8;
    const int r0c = min(row0, NPIX - 1), r1c = min(row0 + 8, NPIX - 1);
    const uint2 qa0 = Qp[(size_t)r0c * 8 + t];
    const uint2 qa1 = Qp[(size_t)r1c * 8 + t];
    const uint2 qa2 = Qp[(size_t)r0c * 8 + t + 4];
    const uint2 qa3 = Qp[(size_t)r1c * 8 + t + 4];
    const uint32_t Qhi[4] = {qa0.x, qa1.x, qa2.x, qa3.x};
    const uint32_t Qlo[4] = {qa0.y, qa1.y, qa2.y, qa3.y};

    const uint2*    Kp = g_Kp + (size_t)bh * NPIX * 8;
    const uint32_t* Vp = g_Vh + (size_t)bh * DV * (NPIX / 2);

    float o[8][4] = {};
    float rs0 = 0.f, rs1 = 0.f;
    float m0 = -3.0e38f, m1 = -3.0e38f;

    const int skey = tid >> 2, scol = (tid & 3) * 2;
    const int sd   = tid >> 2, svc  = (tid & 3) * 8;

    for (int kt = 0; kt < NT64; kt++) {
        const int k0 = kt * 64;

        __syncthreads();
        {   // stage K tile
            uint4 kv = *(const uint4*)(Kp + (size_t)(k0 + skey) * 8 + scol);
            sK[skey][scol]     = make_uint2(kv.x, kv.y);
            sK[skey][scol + 1] = make_uint2(kv.z, kv.w);
        }
        {   // stage V tile
            const uint32_t* vgp = Vp + (size_t)sd * (NPIX / 2) + (k0 >> 1) + svc;
            uint4 a = *(const uint4*)vgp;
            uint4 b = *(const uint4*)(vgp + 4);
            *(uint2*)&sV[sd][svc]     = make_uint2(a.x, a.y);
            *(uint2*)&sV[sd][svc + 2] = make_uint2(a.z, a.w);
            *(uint2*)&sV[sd][svc + 4] = make_uint2(b.x, b.y);
            *(uint2*)&sV[sd][svc + 6] = make_uint2(b.z, b.w);
        }
        __syncthreads();

        // ---- S = Q K^T ----
        float s[8][4] = {};
        #pragma unroll
        for (int j = 0; j < 8; j++) {
            const uint2 b0 = sK[8 * j + g][t];
            const uint2 b1 = sK[8 * j + g][t + 4];
            mma16816h(s[j], Qhi, b0.x, b1.x);
            mma16816h(s[j], Qhi, b0.y, b1.y);
            mma16816h(s[j], Qlo, b0.x, b1.x);
        }

        // ---- online max ----
        float mt0 = s[0][0], mt1 = s[0][2];
        #pragma unroll
        for (int j = 0; j < 8; j++) {
            mt0 = fmaxf(mt0, fmaxf(s[j][0], s[j][1]));
            mt1 = fmaxf(mt1, fmaxf(s[j][2], s[j][3]));
        }
        mt0 = fmaxf(mt0, __shfl_xor_sync(0xffffffffu, mt0, 1));
        mt0 = fmaxf(mt0, __shfl_xor_sync(0xffffffffu, mt0, 2));
        mt1 = fmaxf(mt1, __shfl_xor_sync(0xffffffffu, mt1, 1));
        mt1 = fmaxf(mt1, __shfl_xor_sync(0xffffffffu, mt1, 2));
        const float mn0 = fmaxf(m0, mt0), mn1 = fmaxf(m1, mt1);
        const float c0 = __expf(m0 - mn0), c1 = __expf(m1 - mn1);
        m0 = mn0; m1 = mn1;
        rs0 *= c0; rs1 *= c1;
        #pragma unroll
        for (int j = 0; j < 8; j++) {
            o[j][0] *= c0; o[j][1] *= c0;
            o[j][2] *= c1; o[j][3] *= c1;
        }

        // ---- P = exp(S - m), rowsum ----
        #pragma unroll
        for (int j = 0; j < 8; j++) {
            s[j][0] = __expf(s[j][0] - mn0);
            s[j][1] = __expf(s[j][1] - mn0);
            s[j][2] = __expf(s[j][2] - mn1);
            s[j][3] = __expf(s[j][3] - mn1);
            rs0 += s[j][0] + s[j][1];
            rs1 += s[j][2] + s[j][3];
        }

        // ---- O += P V ----
        #pragma unroll
        for (int ss = 0; ss < 4; ss++) {
            uint32_t ph[4];
            ph[0] = packh(s[2*ss  ][0], s[2*ss  ][1]);
            ph[1] = packh(s[2*ss  ][2], s[2*ss  ][3]);
            ph[2] = packh(s[2*ss+1][0], s[2*ss+1][1]);
            ph[3] = packh(s[2*ss+1][2], s[2*ss+1][3]);
            const int col = 8 * ss + t;
            #pragma unroll
            for (int j = 0; j < 8; j++) {
                const uint32_t b0 = sV[8 * j + g][col];
                const uint32_t b1 = sV[8 * j + g][col + 4];
                mma16816h(o[j], ph, b0, b1);
            }
        }
    }

    rs0 += __shfl_xor_sync(0xffffffffu, rs0, 1);
    rs0 += __shfl_xor_sync(0xffffffffu, rs0, 2);
    rs1 += __shfl_xor_sync(0xffffffffu, rs1, 1);
    rs1 += __shfl_xor_sync(0xffffffffu, rs1, 2);
    const float inv0 = 1.f / rs0;
    const float inv1 = 1.f / rs1;

    // ---- write relu(O) split pairs: dpair = 4j+t (d = 8j+2t, +1) ----
    uint32_t hi, lo;
    if (row0 < NPIX) {
        uint2* ob = g_Oph + ((size_t)bh * NPIX + row0) * 32;
        #pragma unroll
        for (int j = 0; j < 8; j++) {
            split2h(fmaxf(o[j][0] * inv0, 0.f), fmaxf(o[j][1] * inv0, 0.f), hi, lo);
            ob[4 * j + t] = make_uint2(hi, lo);
        }
        if (row0 + 8 < NPIX) {
            uint2* ob1 = ob + 8 * 32;
            #pragma unroll
            for (int j = 0; j < 8; j++) {
                split2h(fmaxf(o[j][2] * inv1, 0.f), fmaxf(o[j][3] * inv1, 0.f), hi, lo);
                ob1[4 * j + t] = make_uint2(hi, lo);
            }
        }
    }
}

// ---------------------------------------------------------------------------
// K3: projection via MMA. grid (25, 3, 2), block 256 (8 warps).
// Block: 128 pixels x 128 oc, K=512 in 32 steps. A = relu(O) pairs (g_Oph).
// ---------------------------------------------------------------------------
__global__ __launch_bounds__(256, 2) void proj_mma(float* __restrict__ out)
{
    __shared__ uint2 sW[128][9];

    const int b = blockIdx.z;
    const int oc0 = blockIdx.y * 128;
    const int pix0 = blockIdx.x * 128;
    const int tid = threadIdx.x;
    const int w = tid >> 5, lane = tid & 31;
    const int g = lane >> 2, t = lane & 3;
    const int row0 = pix0 + 16 * w + g;
    const int r0c = min(row0, NPIX - 1), r1c = min(row0 + 8, NPIX - 1);

    float acc[16][4] = {};

    for (int s = 0; s < 32; s++) {
        __syncthreads();
        {
            const int i0 = tid * 4;
            #pragma unroll
            for (int i = 0; i < 4; i++) {
                const int idx = i0 + i, rr = idx >> 3, pp = idx & 7;
                sW[rr][pp] = g_Wpp[(size_t)(oc0 + rr) * DHP + 8 * s + pp];
            }
        }
        __syncthreads();

        const int head = s >> 2, dp = 8 * (s & 3) + t;
        const uint2* Ob = g_Oph + ((size_t)(b * HEADS + head) * NPIX) * 32;
        const uint2 a0 = Ob[(size_t)r0c * 32 + dp];
        const uint2 a1 = Ob[(size_t)r1c * 32 + dp];
        const uint2 a2 = Ob[(size_t)r0c * 32 + dp + 4];
        const uint2 a3 = Ob[(size_t)r1c * 32 + dp + 4];
        const uint32_t Ah[4] = {a0.x, a1.x, a2.x, a3.x};
        const uint32_t Al[4] = {a0.y, a1.y, a2.y, a3.y};

        #pragma unroll
        for (int j = 0; j < 16; j++) {
            const uint2 b0 = sW[8 * j + g][t];
            const uint2 b1 = sW[8 * j + g][t + 4];
            mma16816h(acc[j], Ah, b0.x, b1.x);
            mma16816h(acc[j], Ah, b0.y, b1.y);
            mma16816h(acc[j], Al, b0.x, b1.x);
        }
    }

    #pragma unroll
    for (int j = 0; j < 16; j++) {
        const int oc = oc0 + 8 * j + 2 * t;
        const float s0 = g_shiftP[oc], s1 = g_shiftP[oc + 1];
        float* ob = out + ((size_t)b * OCOUT + oc) * NPIX;
        if (row0 < NPIX) {
            ob[row0] = acc[j][0] + s0;
            ob[NPIX + row0] = acc[j][1] + s1;
        }
        if (row0 + 8 < NPIX) {
            ob[row0 + 8] = acc[j][2] + s0;
            ob[NPIX + row0 + 8] = acc[j][3] + s1;
        }
    }
}

// ---------------------------------------------------------------------------
extern "C" void kernel_launch(void* const* d_in, const int* in_sizes, int n_in,
                              void* d_out, int out_size)
{
    (void)in_sizes; (void)n_in; (void)out_size;
    const float* x   = (const float*)d_in[0];
    const float* wq  = (const float*)d_in[1];
    const float* qg  = (const float*)d_in[2];
    const float* qb  = (const float*)d_in[3];
    const float* qm  = (const float*)d_in[4];
    const float* qv  = (const float*)d_in[5];
    const float* wk  = (const float*)d_in[6];
    const float* kg  = (const float*)d_in[7];
    const float* kb  = (const float*)d_in[8];
    const float* km  = (const float*)d_in[9];
    const float* kvv = (const float*)d_in[10];
    const float* wv  = (const float*)d_in[11];
    const float* vg  = (const float*)d_in[12];
    const float* vb  = (const float*)d_in[13];
    const float* vm  = (const float*)d_in[14];
    const float* vvv = (const float*)d_in[15];
    const float* wp  = (const float*)d_in[16];
    const float* pg  = (const float*)d_in[17];
    const float* pb  = (const float*)d_in[18];
    const float* pm  = (const float*)d_in[19];
    const float* pvv = (const float*)d_in[20];
    float* out = (float*)d_out;

    prep_x<<<dim3(NT64, 6, BATCH), 256>>>(x);
    prep_w<<<dim3(1152), 256>>>(wq, wk, wv, wp,
                                qg, qb, qm, qv,
                                kg, kb, km, kvv,
                                vg, vb, vm, vvv,
                                pg, pb, pm, pvv);
    qkv_mma<<<dim3(QT128, 6, BATCH), 256>>>();
    attn_mma_kernel<<<dim3(QT128, BH), 256>>>();
    proj_mma<<<dim3(QT128, 3, BATCH), 256>>>(out);
}

// round 8
// speedup vs baseline: 4.0576x; 1.0981x over previous
#include <cuda_runtime.h>
#include <cuda_fp16.h>
#include <cstdint>

// ---------------------------------------------------------------------------
// EfficientViT attention block — all three GEMMs on tensor cores (mma.sync
// m16n8k16 fp16), fp32-accuracy via hi/lo split operands (3-MMA products).
//   P1: prep_x  : x -> transposed fp16 hi/lo pairs  g_Xp[b][pix][icpair]
//   P2: prep_w  : BN-scale-folded, split weights g_Wall (qkv) / g_Wpp (proj)
//   K1: qkv_mma : Q/K (split pairs) + V (transposed fp16) via MMA
//   K2: attn    : softmax(QK^T)V, online max, double-buffered K/V staging
//   K3: proj_mma: out = Wp @ relu(O) + shift via MMA
// ---------------------------------------------------------------------------

namespace {
constexpr int BATCH = 2;
constexpr int CIN   = 384;
constexpr int NPIX  = 3136;     // 56*56
constexpr int HEADS = 8;
constexpr int KD    = 16;
constexpr int DV    = 64;
constexpr int DH    = 512;
constexpr int OCOUT = 384;
constexpr int BH    = BATCH * HEADS;
constexpr int NT64  = NPIX / 64;             // 49 key tiles / q tiles of 64
constexpr int QT128 = (NPIX + 127) / 128;    // 25 pixel tiles of 128 (GEMMs)
constexpr int ICP   = CIN / 2;               // 192 ic-pairs
constexpr int DHP   = DH / 2;                // 256 ic-pairs for proj
constexpr float EPSBN = 1e-5f;
}

// scratch (static device arrays: allocation-free per harness rules)
__device__ __align__(16) uint2    g_Xp[BATCH * NPIX * ICP];        // x^T split
__device__ __align__(16) uint2    g_Wall[(256 + DH) * ICP];        // 768 rows q,k,v
__device__ __align__(16) uint2    g_Wpp[OCOUT * DHP];              // proj W
__device__            float       g_shiftAll[768];
__device__            float       g_shiftP[OCOUT];
__device__ __align__(16) uint2    g_Qp[BH * NPIX * 8];             // [bh][pix][kdpair]{hi,lo}
__device__ __align__(16) uint2    g_Kp[BH * NPIX * 8];
__device__ __align__(16) uint32_t g_Vh[BH * DV * (NPIX / 2)];      // [bh][d][pixpair] f16x2
__device__ __align__(16) uint2    g_Oph[BH * NPIX * (DV / 2)];     // relu(O) split [bh][pix][dpair]

// split fp32 pair -> f16x2 hi (v0 low half) + f16x2 lo (residuals)
__device__ __forceinline__ void split2h(float v0, float v1, uint32_t& hi, uint32_t& lo) {
    __half h0 = __float2half_rn(v0), h1 = __float2half_rn(v1);
    hi = ((uint32_t)__half_as_ushort(h1) << 16) | (uint32_t)__half_as_ushort(h0);
    float r0 = v0 - __half2float(h0);
    float r1 = v1 - __half2float(h1);
    asm("cvt.rn.f16x2.f32 %0, %1, %2;" : "=r"(lo) : "f"(r1), "f"(r0));
}
__device__ __forceinline__ uint32_t packh(float v0, float v1) {
    uint32_t d; asm("cvt.rn.f16x2.f32 %0, %1, %2;" : "=r"(d) : "f"(v1), "f"(v0)); return d;
}

// mma.sync m16n8k16 fp16 -> f32 accum
// A frag: {(g,t),(g+8,t),(g,t+4),(g+8,t+4)} pair-granularity; B: n=g, kpair=t/t+4;
// C: row=g/g+8, col=2t/2t+1.   (empirically validated rounds 5-7)
__device__ __forceinline__ void mma16816h(float* c, const uint32_t* a, uint32_t b0, uint32_t b1) {
    asm volatile("mma.sync.aligned.m16n8k16.row.col.f32.f16.f16.f32 "
        "{%0,%1,%2,%3}, {%4,%5,%6,%7}, {%8,%9}, {%0,%1,%2,%3};"
        : "+f"(c[0]), "+f"(c[1]), "+f"(c[2]), "+f"(c[3])
        : "r"(a[0]), "r"(a[1]), "r"(a[2]), "r"(a[3]), "r"(b0), "r"(b1));
}

// ---------------------------------------------------------------------------
// P1: transpose + split x. grid (49, 6, 2), block 256. 64 pix x 64 ch per blk.
// ---------------------------------------------------------------------------
__global__ __launch_bounds__(256) void prep_x(const float* __restrict__ x)
{
    __shared__ float s[8][66];
    const int pix0 = blockIdx.x * 64;
    const int cc0  = blockIdx.y * 64;
    const int b    = blockIdx.z;
    const int tid  = threadIdx.x;
    const int lr = tid >> 5, lc = (tid & 31) * 2;
    const int pix = tid >> 2, gp = tid & 3;

    for (int cc = cc0; cc < cc0 + 64; cc += 8) {
        float2 v = *(const float2*)(x + ((size_t)b * CIN + cc + lr) * NPIX + pix0 + lc);
        s[lr][lc] = v.x; s[lr][lc + 1] = v.y;
        __syncthreads();
        uint32_t hi, lo;
        split2h(s[2 * gp][pix], s[2 * gp + 1][pix], hi, lo);
        g_Xp[((size_t)b * NPIX + pix0 + pix) * ICP + (cc >> 1) + gp] = make_uint2(hi, lo);
        __syncthreads();
    }
}

// ---------------------------------------------------------------------------
// P2: fold BN scale into weights, split fp16 hi/lo; compute shifts.
// grid 1152, block 256. rows 0..767 -> g_Wall (q,k,v), 768..1151 -> g_Wpp.
// ---------------------------------------------------------------------------
__global__ __launch_bounds__(256) void prep_w(
    const float* __restrict__ wq, const float* __restrict__ wk,
    const float* __restrict__ wv, const float* __restrict__ wp,
    const float* __restrict__ qg, const float* __restrict__ qb, const float* __restrict__ qm, const float* __restrict__ qv,
    const float* __restrict__ kg, const float* __restrict__ kb, const float* __restrict__ km, const float* __restrict__ kvv,
    const float* __restrict__ vg, const float* __restrict__ vb, const float* __restrict__ vm, const float* __restrict__ vvv,
    const float* __restrict__ pg, const float* __restrict__ pb, const float* __restrict__ pm, const float* __restrict__ pvv)
{
    const int r = blockIdx.x, t = threadIdx.x;
    if (r < 768) {
        const float *w, *gg, *bb, *mm, *vx; int rr;
        if (r < 128)      { w = wq; gg = qg; bb = qb; mm = qm; vx = qv;  rr = r; }
        else if (r < 256) { w = wk; gg = kg; bb = kb; mm = km; vx = kvv; rr = r - 128; }
        else              { w = wv; gg = vg; bb = vb; mm = vm; vx = vvv; rr = r - 256; }
        const float sc = gg[rr] * rsqrtf(vx[rr] + EPSBN);
        if (t == 0) g_shiftAll[r] = bb[rr] - mm[rr] * sc;
        if (t < ICP) {
            float2 w2 = *(const float2*)(w + (size_t)rr * CIN + 2 * t);
            uint32_t hi, lo; split2h(w2.x * sc, w2.y * sc, hi, lo);
            g_Wall[(size_t)r * ICP + t] = make_uint2(hi, lo);
        }
    } else {
        const int rp = r - 768;
        const float sc = pg[rp] * rsqrtf(pvv[rp] + EPSBN);
        if (t == 0) g_shiftP[rp] = pb[rp] - pm[rp] * sc;
        float2 w2 = *(const float2*)(wp + (size_t)rp * DH + 2 * t);
        uint32_t hi, lo; split2h(w2.x * sc, w2.y * sc, hi, lo);
        g_Wpp[(size_t)rp * DHP + t] = make_uint2(hi, lo);
    }
}

// ---------------------------------------------------------------------------
// K1: QKV projection via MMA. grid (25, 6, 2), block 256 (8 warps).
// Block: 128 pixels (M) x 128 out-channels (N), K=384 in 24 steps.
// by: 0 -> Q(oc 0-127), 1 -> K, 2..5 -> V(oc 256-767).
// ---------------------------------------------------------------------------
__global__ __launch_bounds__(256, 2) void qkv_mma()
{
    __shared__ uint2 sW[128][9];

    const int by  = blockIdx.y, b = blockIdx.z;
    const int oc0 = by * 128;
    const int pix0 = blockIdx.x * 128;
    const int tid = threadIdx.x;
    const int w   = tid >> 5, lane = tid & 31;
    const int g   = lane >> 2, t = lane & 3;
    const int row0 = pix0 + 16 * w + g;
    const int r0c = min(row0, NPIX - 1), r1c = min(row0 + 8, NPIX - 1);

    const uint2* Xb0 = g_Xp + (size_t)b * NPIX * ICP + (size_t)r0c * ICP;
    const uint2* Xb1 = g_Xp + (size_t)b * NPIX * ICP + (size_t)r1c * ICP;

    float acc[16][4] = {};

    for (int s = 0; s < 24; s++) {
        __syncthreads();
        {   // stage 128 oc x 8 pairs of W
            const int i0 = tid * 4;
            #pragma unroll
            for (int i = 0; i < 4; i++) {
                const int idx = i0 + i, rr = idx >> 3, pp = idx & 7;
                sW[rr][pp] = g_Wall[(size_t)(oc0 + rr) * ICP + 8 * s + pp];
            }
        }
        __syncthreads();

        const uint2 a0 = Xb0[8 * s + t];
        const uint2 a1 = Xb1[8 * s + t];
        const uint2 a2 = Xb0[8 * s + t + 4];
        const uint2 a3 = Xb1[8 * s + t + 4];
        const uint32_t Ah[4] = {a0.x, a1.x, a2.x, a3.x};
        const uint32_t Al[4] = {a0.y, a1.y, a2.y, a3.y};

        #pragma unroll
        for (int j = 0; j < 16; j++) {
            const uint2 b0 = sW[8 * j + g][t];
            const uint2 b1 = sW[8 * j + g][t + 4];
            mma16816h(acc[j], Ah, b0.x, b1.x);
            mma16816h(acc[j], Ah, b0.y, b1.y);
            mma16816h(acc[j], Al, b0.x, b1.x);
        }
    }

    if (by < 2) {
        // ---- Q or K: kd-pairs are in-lane (cols 2t, 2t+1) ----
        uint2* QK = (by == 0) ? g_Qp : g_Kp;
        #pragma unroll
        for (int j = 0; j < 16; j++) {
            const int ocl = 8 * j + 2 * t;
            const float s0 = g_shiftAll[oc0 + ocl], s1 = g_shiftAll[oc0 + ocl + 1];
            const int head = ocl >> 4, kdp = (ocl & 15) >> 1;
            uint2* base = QK + ((size_t)(b * HEADS + head) * NPIX) * 8 + kdp;
            uint32_t hi, lo;
            if (row0 < NPIX) {
                split2h(acc[j][0] + s0, acc[j][1] + s1, hi, lo);
                base[(size_t)row0 * 8] = make_uint2(hi, lo);
            }
            if (row0 + 8 < NPIX) {
                split2h(acc[j][2] + s0, acc[j][3] + s1, hi, lo);
                base[(size_t)(row0 + 8) * 8] = make_uint2(hi, lo);
            }
        }
    } else {
        // ---- V: pixel-pairs via shfl (neighbor pixel = lane+4) ----
        #pragma unroll
        for (int j = 0; j < 16; j++) {
            const int ocv = (by - 2) * 128 + 8 * j + 2 * t;
            const float s0 = g_shiftAll[256 + ocv], s1 = g_shiftAll[256 + ocv + 1];
            const int head = ocv >> 6, d = ocv & 63;
            const float v00 = acc[j][0] + s0, v01 = acc[j][1] + s1;
            const float v10 = acc[j][2] + s0, v11 = acc[j][3] + s1;
            const float n00 = __shfl_down_sync(0xffffffffu, v00, 4);
            const float n01 = __shfl_down_sync(0xffffffffu, v01, 4);
            const float n10 = __shfl_down_sync(0xffffffffu, v10, 4);
            const float n11 = __shfl_down_sync(0xffffffffu, v11, 4);
            if (!(g & 1)) {
                uint32_t* vb = g_Vh + ((size_t)(b * HEADS + head) * DV + d) * (NPIX / 2);
                const int pp0 = row0 >> 1, pp1 = (row0 + 8) >> 1;
                if (row0 + 1 < NPIX) {
                    vb[pp0] = packh(v00, n00);
                    vb[(NPIX / 2) + pp0] = packh(v01, n01);
                }
                if (row0 + 9 < NPIX) {
                    vb[pp1] = packh(v10, n10);
                    vb[(NPIX / 2) + pp1] = packh(v11, n11);
                }
            }
        }
    }
}

// ---------------------------------------------------------------------------
// K2: attention. grid (49, 16), block 128 (4 warps), q-tile 64 (exact).
// Double-buffered K/V smem staging, register prefetch 2 tiles ahead,
// single __syncthreads per key tile.
// ---------------------------------------------------------------------------
__global__ __launch_bounds__(128, 4) void attn_mma_kernel()
{
    __shared__ __align__(16) uint2    sK[2][64][10];   // [stage][key][kdpair{hi,lo}] pad->80B rows
    __shared__ __align__(16) uint32_t sV[2][64][36];   // [stage][d][keypair f16x2]  pad->144B rows

    const int bh  = blockIdx.y;
    const int q0  = blockIdx.x * 64;
    const int tid = threadIdx.x;
    const int w   = tid >> 5, lane = tid & 31;
    const int g   = lane >> 2, t = lane & 3;
    const int row0 = q0 + w * 16 + g;            // always < NPIX (exact tiling)

    // ---- Q fragments (hi/lo), loaded once ----
    const uint2* Qp = g_Qp + (size_t)bh * NPIX * 8;
    const uint2 qa0 = Qp[(size_t)row0 * 8 + t];
    const uint2 qa1 = Qp[(size_t)(row0 + 8) * 8 + t];
    const uint2 qa2 = Qp[(size_t)row0 * 8 + t + 4];
    const uint2 qa3 = Qp[(size_t)(row0 + 8) * 8 + t + 4];
    const uint32_t Qhi[4] = {qa0.x, qa1.x, qa2.x, qa3.x};
    const uint32_t Qlo[4] = {qa0.y, qa1.y, qa2.y, qa3.y};

    const uint4* Kp4 = (const uint4*)(g_Kp + (size_t)bh * NPIX * 8);      // 4 uint4 per key
    const uint4* Vp4 = (const uint4*)(g_Vh + (size_t)bh * DV * (NPIX/2)); // 392 uint4 per d-row

    // loader indices (2 K-chunks + 4 V-chunks per thread)
    const int kr0 = tid >> 2,          ks0 = tid & 3;          // idx = tid
    const int kr1 = (tid + 128) >> 2,  ks1 = tid & 3;          // idx = tid+128
    const int vr[4] = { tid >> 3, (tid + 128) >> 3, (tid + 256) >> 3, (tid + 384) >> 3 };
    const int vs    = tid & 7;

    uint4 kf0, kf1, vf[4];

    auto load_tile = [&](int kt) {
        const int kb = kt * 64;
        kf0 = Kp4[(size_t)(kb + kr0) * 4 + ks0];
        kf1 = Kp4[(size_t)(kb + kr1) * 4 + ks1];
        #pragma unroll
        for (int i = 0; i < 4; i++)
            vf[i] = Vp4[(size_t)vr[i] * 392 + kt * 8 + vs];
    };
    auto store_tile = [&](int st) {
        *(uint4*)&sK[st][kr0][ks0 * 2] = kf0;
        *(uint4*)&sK[st][kr1][ks1 * 2] = kf1;
        #pragma unroll
        for (int i = 0; i < 4; i++)
            *(uint4*)&sV[st][vr[i]][vs * 4] = vf[i];
    };

    float o[8][4] = {};
    float rs0 = 0.f, rs1 = 0.f;
    float m0 = -3.0e38f, m1 = -3.0e38f;

    // ---- pipeline prologue ----
    load_tile(0);
    store_tile(0);
    load_tile(1);
    __syncthreads();

    for (int kt = 0; kt < NT64; kt++) {
        const int cur = kt & 1;

        if (kt + 1 < NT64) {
            store_tile(1 - cur);                 // stage for tile kt+1 (safe: last read at kt-1)
            if (kt + 2 < NT64) load_tile(kt + 2);
        }

        // ---- S = Q K^T : 8 key-groups x 3 split MMAs ----
        float s[8][4] = {};
        #pragma unroll
        for (int j = 0; j < 8; j++) {
            const uint2 b0 = sK[cur][8 * j + g][t];
            const uint2 b1 = sK[cur][8 * j + g][t + 4];
            mma16816h(s[j], Qhi, b0.x, b1.x);
            mma16816h(s[j], Qhi, b0.y, b1.y);
            mma16816h(s[j], Qlo, b0.x, b1.x);
        }

        // ---- online max ----
        float mt0 = s[0][0], mt1 = s[0][2];
        #pragma unroll
        for (int j = 0; j < 8; j++) {
            mt0 = fmaxf(mt0, fmaxf(s[j][0], s[j][1]));
            mt1 = fmaxf(mt1, fmaxf(s[j][2], s[j][3]));
        }
        mt0 = fmaxf(mt0, __shfl_xor_sync(0xffffffffu, mt0, 1));
        mt0 = fmaxf(mt0, __shfl_xor_sync(0xffffffffu, mt0, 2));
        mt1 = fmaxf(mt1, __shfl_xor_sync(0xffffffffu, mt1, 1));
        mt1 = fmaxf(mt1, __shfl_xor_sync(0xffffffffu, mt1, 2));
        const float mn0 = fmaxf(m0, mt0), mn1 = fmaxf(m1, mt1);
        const float c0 = __expf(m0 - mn0), c1 = __expf(m1 - mn1);
        m0 = mn0; m1 = mn1;
        rs0 *= c0; rs1 *= c1;
        #pragma unroll
        for (int j = 0; j < 8; j++) {
            o[j][0] *= c0; o[j][1] *= c0;
            o[j][2] *= c1; o[j][3] *= c1;
        }

        // ---- P = exp(S - m), rowsum ----
        #pragma unroll
        for (int j = 0; j < 8; j++) {
            s[j][0] = __expf(s[j][0] - mn0);
            s[j][1] = __expf(s[j][1] - mn0);
            s[j][2] = __expf(s[j][2] - mn1);
            s[j][3] = __expf(s[j][3] - mn1);
            rs0 += s[j][0] + s[j][1];
            rs1 += s[j][2] + s[j][3];
        }

        // ---- O += P V ----
        #pragma unroll
        for (int ss = 0; ss < 4; ss++) {
            uint32_t ph[4];
            ph[0] = packh(s[2*ss  ][0], s[2*ss  ][1]);
            ph[1] = packh(s[2*ss  ][2], s[2*ss  ][3]);
            ph[2] = packh(s[2*ss+1][0], s[2*ss+1][1]);
            ph[3] = packh(s[2*ss+1][2], s[2*ss+1][3]);
            const int col = 8 * ss + t;
            #pragma unroll
            for (int j = 0; j < 8; j++) {
                const uint32_t b0 = sV[cur][8 * j + g][col];
                const uint32_t b1 = sV[cur][8 * j + g][col + 4];
                mma16816h(o[j], ph, b0, b1);
            }
        }

        __syncthreads();   // stage cur consumed; stage 1-cur stores visible
    }

    rs0 += __shfl_xor_sync(0xffffffffu, rs0, 1);
    rs0 += __shfl_xor_sync(0xffffffffu, rs0, 2);
    rs1 += __shfl_xor_sync(0xffffffffu, rs1, 1);
    rs1 += __shfl_xor_sync(0xffffffffu, rs1, 2);
    const float inv0 = 1.f / rs0;
    const float inv1 = 1.f / rs1;

    // ---- write relu(O) split pairs: dpair = 4j+t (d = 8j+2t, +1) ----
    uint32_t hi, lo;
    uint2* ob  = g_Oph + ((size_t)bh * NPIX + row0) * 32;
    uint2* ob1 = ob + 8 * 32;
    #pragma unroll
    for (int j = 0; j < 8; j++) {
        split2h(fmaxf(o[j][0] * inv0, 0.f), fmaxf(o[j][1] * inv0, 0.f), hi, lo);
        ob[4 * j + t] = make_uint2(hi, lo);
        split2h(fmaxf(o[j][2] * inv1, 0.f), fmaxf(o[j][3] * inv1, 0.f), hi, lo);
        ob1[4 * j + t] = make_uint2(hi, lo);
    }
}

// ---------------------------------------------------------------------------
// K3: projection via MMA. grid (25, 3, 2), block 256 (8 warps).
// Block: 128 pixels x 128 oc, K=512 in 32 steps. A = relu(O) pairs (g_Oph).
// ---------------------------------------------------------------------------
__global__ __launch_bounds__(256, 2) void proj_mma(float* __restrict__ out)
{
    __shared__ uint2 sW[128][9];

    const int b = blockIdx.z;
    const int oc0 = blockIdx.y * 128;
    const int pix0 = blockIdx.x * 128;
    const int tid = threadIdx.x;
    const int w = tid >> 5, lane = tid & 31;
    const int g = lane >> 2, t = lane & 3;
    const int row0 = pix0 + 16 * w + g;
    const int r0c = min(row0, NPIX - 1), r1c = min(row0 + 8, NPIX - 1);

    float acc[16][4] = {};

    for (int s = 0; s < 32; s++) {
        __syncthreads();
        {
            const int i0 = tid * 4;
            #pragma unroll
            for (int i = 0; i < 4; i++) {
                const int idx = i0 + i, rr = idx >> 3, pp = idx & 7;
                sW[rr][pp] = g_Wpp[(size_t)(oc0 + rr) * DHP + 8 * s + pp];
            }
        }
        __syncthreads();

        const int head = s >> 2, dp = 8 * (s & 3) + t;
        const uint2* Ob = g_Oph + ((size_t)(b * HEADS + head) * NPIX) * 32;
        const uint2 a0 = Ob[(size_t)r0c * 32 + dp];
        const uint2 a1 = Ob[(size_t)r1c * 32 + dp];
        const uint2 a2 = Ob[(size_t)r0c * 32 + dp + 4];
        const uint2 a3 = Ob[(size_t)r1c * 32 + dp + 4];
        const uint32_t Ah[4] = {a0.x, a1.x, a2.x, a3.x};
        const uint32_t Al[4] = {a0.y, a1.y, a2.y, a3.y};

        #pragma unroll
        for (int j = 0; j < 16; j++) {
            const uint2 b0 = sW[8 * j + g][t];
            const uint2 b1 = sW[8 * j + g][t + 4];
            mma16816h(acc[j], Ah, b0.x, b1.x);
            mma16816h(acc[j], Ah, b0.y, b1.y);
            mma16816h(acc[j], Al, b0.x, b1.x);
        }
    }

    #pragma unroll
    for (int j = 0; j < 16; j++) {
        const int oc = oc0 + 8 * j + 2 * t;
        const float s0 = g_shiftP[oc], s1 = g_shiftP[oc + 1];
        float* ob = out + ((size_t)b * OCOUT + oc) * NPIX;
        if (row0 < NPIX) {
            ob[row0] = acc[j][0] + s0;
            ob[NPIX + row0] = acc[j][1] + s1;
        }
        if (row0 + 8 < NPIX) {
            ob[row0 + 8] = acc[j][2] + s0;
            ob[NPIX + row0 + 8] = acc[j][3] + s1;
        }
    }
}

// ---------------------------------------------------------------------------
extern "C" void kernel_launch(void* const* d_in, const int* in_sizes, int n_in,
                              void* d_out, int out_size)
{
    (void)in_sizes; (void)n_in; (void)out_size;
    const float* x   = (const float*)d_in[0];
    const float* wq  = (const float*)d_in[1];
    const float* qg  = (const float*)d_in[2];
    const float* qb  = (const float*)d_in[3];
    const float* qm  = (const float*)d_in[4];
    const float* qv  = (const float*)d_in[5];
    const float* wk  = (const float*)d_in[6];
    const float* kg  = (const float*)d_in[7];
    const float* kb  = (const float*)d_in[8];
    const float* km  = (const float*)d_in[9];
    const float* kvv = (const float*)d_in[10];
    const float* wv  = (const float*)d_in[11];
    const float* vg  = (const float*)d_in[12];
    const float* vb  = (const float*)d_in[13];
    const float* vm  = (const float*)d_in[14];
    const float* vvv = (const float*)d_in[15];
    const float* wp  = (const float*)d_in[16];
    const float* pg  = (const float*)d_in[17];
    const float* pb  = (const float*)d_in[18];
    const float* pm  = (const float*)d_in[19];
    const float* pvv = (const float*)d_in[20];
    float* out = (float*)d_out;

    prep_x<<<dim3(NT64, 6, BATCH), 256>>>(x);
    prep_w<<<dim3(1152), 256>>>(wq, wk, wv, wp,
                                qg, qb, qm, qv,
                                kg, kb, km, kvv,
                                vg, vb, vm, vvv,
                                pg, pb, pm, pvv);
    qkv_mma<<<dim3(QT128, 6, BATCH), 256>>>();
    attn_mma_kernel<<<dim3(NT64, BH), 128>>>();
    proj_mma<<<dim3(QT128, 3, BATCH), 256>>>(out);
}

// round 9
// speedup vs baseline: 4.3898x; 1.0819x over previous
#include <cuda_runtime.h>
#include <cuda_fp16.h>
#include <cstdint>

// ---------------------------------------------------------------------------
// EfficientViT attention block — all three GEMMs on tensor cores (mma.sync
// m16n8k16 fp16), fp32-accuracy via hi/lo split operands (3-MMA products).
//   P1: prep_x  : x -> transposed fp16 hi/lo pairs  g_Xp[b][pix][icpair]
//   P2: prep_w  : BN-scale-folded, split weights g_Wall (qkv) / g_Wpp (proj)
//   K1: qkv_mma : Q/K (split pairs) + V (transposed, PAIR-PERMUTED fp16)
//   K2: attn    : softmax(QK^T)V, online max, 4-stage cp.async K/V ring
//   K3: proj_mma: out = Wp @ relu(O) + shift via MMA
// ---------------------------------------------------------------------------

namespace {
constexpr int BATCH = 2;
constexpr int CIN   = 384;
constexpr int NPIX  = 3136;     // 56*56
constexpr int HEADS = 8;
constexpr int KD    = 16;
constexpr int DV    = 64;
constexpr int DH    = 512;
constexpr int OCOUT = 384;
constexpr int BH    = BATCH * HEADS;
constexpr int NT64  = NPIX / 64;             // 49 key tiles / q tiles of 64
constexpr int QT128 = (NPIX + 127) / 128;    // 25 pixel tiles of 128 (GEMMs)
constexpr int ICP   = CIN / 2;               // 192 ic-pairs
constexpr int DHP   = DH / 2;                // 256 ic-pairs for proj
constexpr float EPSBN = 1e-5f;

// attn smem ring: 4 stages x (K 64x80B + V 64x144B) = 4 x 14336 = 57344 B
constexpr int STG_BYTES = 64 * 80 + 64 * 144;   // 14336
constexpr int ATTN_SMEM = 4 * STG_BYTES;        // 57344
}

// scratch (static device arrays: allocation-free per harness rules)
__device__ __align__(16) uint2    g_Xp[BATCH * NPIX * ICP];        // x^T split
__device__ __align__(16) uint2    g_Wall[(256 + DH) * ICP];        // 768 rows q,k,v
__device__ __align__(16) uint2    g_Wpp[OCOUT * DHP];              // proj W
__device__            float       g_shiftAll[768];
__device__            float       g_shiftP[OCOUT];
__device__ __align__(16) uint2    g_Qp[BH * NPIX * 8];             // [bh][pix][kdpair]{hi,lo}
__device__ __align__(16) uint2    g_Kp[BH * NPIX * 8];
__device__ __align__(16) uint32_t g_Vh[BH * DV * (NPIX / 2)];      // [bh][d][perm keypair] f16x2
__device__ __align__(16) uint2    g_Oph[BH * NPIX * (DV / 2)];     // relu(O) split [bh][pix][dpair]

// split fp32 pair -> f16x2 hi (v0 low half) + f16x2 lo (residuals)
__device__ __forceinline__ void split2h(float v0, float v1, uint32_t& hi, uint32_t& lo) {
    __half h0 = __float2half_rn(v0), h1 = __float2half_rn(v1);
    hi = ((uint32_t)__half_as_ushort(h1) << 16) | (uint32_t)__half_as_ushort(h0);
    float r0 = v0 - __half2float(h0);
    float r1 = v1 - __half2float(h1);
    asm("cvt.rn.f16x2.f32 %0, %1, %2;" : "=r"(lo) : "f"(r1), "f"(r0));
}
__device__ __forceinline__ uint32_t packh(float v0, float v1) {
    uint32_t d; asm("cvt.rn.f16x2.f32 %0, %1, %2;" : "=r"(d) : "f"(v1), "f"(v0)); return d;
}
__device__ __forceinline__ uint32_t smem_u32(const void* p) {
    uint32_t a;
    asm("{ .reg .u64 t; cvta.to.shared.u64 t, %1; cvt.u32.u64 %0, t; }" : "=r"(a) : "l"(p));
    return a;
}
#define CP_ASYNC16(dst, src) \
    asm volatile("cp.async.cg.shared.global [%0], [%1], 16;" :: "r"(dst), "l"(src))
#define CP_COMMIT() asm volatile("cp.async.commit_group;" ::: "memory")
#define CP_WAIT2()  asm volatile("cp.async.wait_group 2;"  ::: "memory")

// mma.sync m16n8k16 fp16 -> f32 accum
// A frag: {(g,t),(g+8,t),(g,t+4),(g+8,t+4)} pair-granularity; B: n=g, kpair=t/t+4;
// C: row=g/g+8, col=2t/2t+1.   (empirically validated rounds 5-8)
__device__ __forceinline__ void mma16816h(float* c, const uint32_t* a, uint32_t b0, uint32_t b1) {
    asm volatile("mma.sync.aligned.m16n8k16.row.col.f32.f16.f16.f32 "
        "{%0,%1,%2,%3}, {%4,%5,%6,%7}, {%8,%9}, {%0,%1,%2,%3};"
        : "+f"(c[0]), "+f"(c[1]), "+f"(c[2]), "+f"(c[3])
        : "r"(a[0]), "r"(a[1]), "r"(a[2]), "r"(a[3]), "r"(b0), "r"(b1));
}

// ---------------------------------------------------------------------------
// P1: transpose + split x. grid (49, 6, 2), block 256. 64 pix x 64 ch per blk.
// ---------------------------------------------------------------------------
__global__ __launch_bounds__(256) void prep_x(const float* __restrict__ x)
{
    __shared__ float s[8][66];
    const int pix0 = blockIdx.x * 64;
    const int cc0  = blockIdx.y * 64;
    const int b    = blockIdx.z;
    const int tid  = threadIdx.x;
    const int lr = tid >> 5, lc = (tid & 31) * 2;
    const int pix = tid >> 2, gp = tid & 3;

    for (int cc = cc0; cc < cc0 + 64; cc += 8) {
        float2 v = *(const float2*)(x + ((size_t)b * CIN + cc + lr) * NPIX + pix0 + lc);
        s[lr][lc] = v.x; s[lr][lc + 1] = v.y;
        __syncthreads();
        uint32_t hi, lo;
        split2h(s[2 * gp][pix], s[2 * gp + 1][pix], hi, lo);
        g_Xp[((size_t)b * NPIX + pix0 + pix) * ICP + (cc >> 1) + gp] = make_uint2(hi, lo);
        __syncthreads();
    }
}

// ---------------------------------------------------------------------------
// P2: fold BN scale into weights, split fp16 hi/lo; compute shifts.
// grid 1152, block 256. rows 0..767 -> g_Wall (q,k,v), 768..1151 -> g_Wpp.
// ---------------------------------------------------------------------------
__global__ __launch_bounds__(256) void prep_w(
    const float* __restrict__ wq, const float* __restrict__ wk,
    const float* __restrict__ wv, const float* __restrict__ wp,
    const float* __restrict__ qg, const float* __restrict__ qb, const float* __restrict__ qm, const float* __restrict__ qv,
    const float* __restrict__ kg, const float* __restrict__ kb, const float* __restrict__ km, const float* __restrict__ kvv,
    const float* __restrict__ vg, const float* __restrict__ vb, const float* __restrict__ vm, const float* __restrict__ vvv,
    const float* __restrict__ pg, const float* __restrict__ pb, const float* __restrict__ pm, const float* __restrict__ pvv)
{
    const int r = blockIdx.x, t = threadIdx.x;
    if (r < 768) {
        const float *w, *gg, *bb, *mm, *vx; int rr;
        if (r < 128)      { w = wq; gg = qg; bb = qb; mm = qm; vx = qv;  rr = r; }
        else if (r < 256) { w = wk; gg = kg; bb = kb; mm = km; vx = kvv; rr = r - 128; }
        else              { w = wv; gg = vg; bb = vb; mm = vm; vx = vvv; rr = r - 256; }
        const float sc = gg[rr] * rsqrtf(vx[rr] + EPSBN);
        if (t == 0) g_shiftAll[r] = bb[rr] - mm[rr] * sc;
        if (t < ICP) {
            float2 w2 = *(const float2*)(w + (size_t)rr * CIN + 2 * t);
            uint32_t hi, lo; split2h(w2.x * sc, w2.y * sc, hi, lo);
            g_Wall[(size_t)r * ICP + t] = make_uint2(hi, lo);
        }
    } else {
        const int rp = r - 768;
        const float sc = pg[rp] * rsqrtf(pvv[rp] + EPSBN);
        if (t == 0) g_shiftP[rp] = pb[rp] - pm[rp] * sc;
        float2 w2 = *(const float2*)(wp + (size_t)rp * DH + 2 * t);
        uint32_t hi, lo; split2h(w2.x * sc, w2.y * sc, hi, lo);
        g_Wpp[(size_t)rp * DHP + t] = make_uint2(hi, lo);
    }
}

// ---------------------------------------------------------------------------
// K1: QKV projection via MMA. grid (25, 6, 2), block 256 (8 warps).
// Block: 128 pixels (M) x 128 out-channels (N), K=384 in 24 steps.
// by: 0 -> Q(oc 0-127), 1 -> K, 2..5 -> V(oc 256-767).
// ---------------------------------------------------------------------------
__global__ __launch_bounds__(256, 2) void qkv_mma()
{
    __shared__ uint2 sW[128][9];

    const int by  = blockIdx.y, b = blockIdx.z;
    const int oc0 = by * 128;
    const int pix0 = blockIdx.x * 128;
    const int tid = threadIdx.x;
    const int w   = tid >> 5, lane = tid & 31;
    const int g   = lane >> 2, t = lane & 3;
    const int row0 = pix0 + 16 * w + g;
    const int r0c = min(row0, NPIX - 1), r1c = min(row0 + 8, NPIX - 1);

    const uint2* Xb0 = g_Xp + (size_t)b * NPIX * ICP + (size_t)r0c * ICP;
    const uint2* Xb1 = g_Xp + (size_t)b * NPIX * ICP + (size_t)r1c * ICP;

    float acc[16][4] = {};

    for (int s = 0; s < 24; s++) {
        __syncthreads();
        {   // stage 128 oc x 8 pairs of W
            const int i0 = tid * 4;
            #pragma unroll
            for (int i = 0; i < 4; i++) {
                const int idx = i0 + i, rr = idx >> 3, pp = idx & 7;
                sW[rr][pp] = g_Wall[(size_t)(oc0 + rr) * ICP + 8 * s + pp];
            }
        }
        __syncthreads();

        const uint2 a0 = Xb0[8 * s + t];
        const uint2 a1 = Xb1[8 * s + t];
        const uint2 a2 = Xb0[8 * s + t + 4];
        const uint2 a3 = Xb1[8 * s + t + 4];
        const uint32_t Ah[4] = {a0.x, a1.x, a2.x, a3.x};
        const uint32_t Al[4] = {a0.y, a1.y, a2.y, a3.y};

        #pragma unroll
        for (int j = 0; j < 16; j++) {
            const uint2 b0 = sW[8 * j + g][t];
            const uint2 b1 = sW[8 * j + g][t + 4];
            mma16816h(acc[j], Ah, b0.x, b1.x);
            mma16816h(acc[j], Ah, b0.y, b1.y);
            mma16816h(acc[j], Al, b0.x, b1.x);
        }
    }

    if (by < 2) {
        // ---- Q or K: kd-pairs are in-lane (cols 2t, 2t+1) ----
        uint2* QK = (by == 0) ? g_Qp : g_Kp;
        #pragma unroll
        for (int j = 0; j < 16; j++) {
            const int ocl = 8 * j + 2 * t;
            const float s0 = g_shiftAll[oc0 + ocl], s1 = g_shiftAll[oc0 + ocl + 1];
            const int head = ocl >> 4, kdp = (ocl & 15) >> 1;
            uint2* base = QK + ((size_t)(b * HEADS + head) * NPIX) * 8 + kdp;
            uint32_t hi, lo;
            if (row0 < NPIX) {
                split2h(acc[j][0] + s0, acc[j][1] + s1, hi, lo);
                base[(size_t)row0 * 8] = make_uint2(hi, lo);
            }
            if (row0 + 8 < NPIX) {
                split2h(acc[j][2] + s0, acc[j][3] + s1, hi, lo);
                base[(size_t)(row0 + 8) * 8] = make_uint2(hi, lo);
            }
        }
    } else {
        // ---- V: pixel-pairs via shfl; PAIR-PERMUTED layout within 32-pair
        // tiles so that attn's PV B-operand (c, c+4) is one LDS.64:
        // newc = (c & 24) | ((c & 3) << 1) | ((c >> 2) & 1)
        #pragma unroll
        for (int j = 0; j < 16; j++) {
            const int ocv = (by - 2) * 128 + 8 * j + 2 * t;
            const float s0 = g_shiftAll[256 + ocv], s1 = g_shiftAll[256 + ocv + 1];
            const int head = ocv >> 6, d = ocv & 63;
            const float v00 = acc[j][0] + s0, v01 = acc[j][1] + s1;
            const float v10 = acc[j][2] + s0, v11 = acc[j][3] + s1;
            const float n00 = __shfl_down_sync(0xffffffffu, v00, 4);
            const float n01 = __shfl_down_sync(0xffffffffu, v01, 4);
            const float n10 = __shfl_down_sync(0xffffffffu, v10, 4);
            const float n11 = __shfl_down_sync(0xffffffffu, v11, 4);
            if (!(g & 1)) {
                uint32_t* vb = g_Vh + ((size_t)(b * HEADS + head) * DV + d) * (NPIX / 2);
                const int pp0 = row0 >> 1, pp1 = (row0 + 8) >> 1;
                const int c0 = pp0 & 31, c1 = pp1 & 31;
                const int q0i = (pp0 & ~31) | (c0 & 24) | ((c0 & 3) << 1) | ((c0 >> 2) & 1);
                const int q1i = (pp1 & ~31) | (c1 & 24) | ((c1 & 3) << 1) | ((c1 >> 2) & 1);
                if (row0 + 1 < NPIX) {
                    vb[q0i] = packh(v00, n00);
                    vb[(NPIX / 2) + q0i] = packh(v01, n01);
                }
                if (row0 + 9 < NPIX) {
                    vb[q1i] = packh(v10, n10);
                    vb[(NPIX / 2) + q1i] = packh(v11, n11);
                }
            }
        }
    }
}

// ---------------------------------------------------------------------------
// K2: attention. grid (49, 16), block 128 (4 warps), q-tile 64 (exact).
// 4-stage cp.async ring (K 80B-rows, V 144B-rows), single sync per tile.
// Ballot-gated accumulator rescale (bit-identical numerics).
// ---------------------------------------------------------------------------
__global__ __launch_bounds__(128, 4) void attn_mma_kernel()
{
    extern __shared__ __align__(16) unsigned char smem[];

    const int bh  = blockIdx.y;
    const int q0  = blockIdx.x * 64;
    const int tid = threadIdx.x;
    const int lane = tid & 31;
    const int w   = tid >> 5;
    const int g   = lane >> 2, t = lane & 3;
    const int row0 = q0 + w * 16 + g;            // always < NPIX (exact tiling)

    // ---- Q fragments (hi/lo), loaded once ----
    const uint2* Qp = g_Qp + (size_t)bh * NPIX * 8;
    const uint2 qa0 = Qp[(size_t)row0 * 8 + t];
    const uint2 qa1 = Qp[(size_t)(row0 + 8) * 8 + t];
    const uint2 qa2 = Qp[(size_t)row0 * 8 + t + 4];
    const uint2 qa3 = Qp[(size_t)(row0 + 8) * 8 + t + 4];
    const uint32_t Qhi[4] = {qa0.x, qa1.x, qa2.x, qa3.x};
    const uint32_t Qlo[4] = {qa0.y, qa1.y, qa2.y, qa3.y};

    const uint4* Kp4 = (const uint4*)(g_Kp + (size_t)bh * NPIX * 8);      // 4 uint4 per key
    const uint4* Vp4 = (const uint4*)(g_Vh + (size_t)bh * DV * (NPIX/2)); // 392 uint4 per d-row

    const uint32_t smb = smem_u32(smem);
    // loader geometry: K 256 chunks (row=idx>>2, ch=idx&3, off=row*80+ch*16)
    //                  V 512 chunks (row=idx>>3, ch=idx&7, off=row*144+ch*16)
    const int kR0 = tid >> 2,        kC0 = (tid & 3);
    const int kR1 = (tid + 128) >> 2;
    const int vR[4] = { tid >> 3, (tid + 128) >> 3, (tid + 256) >> 3, (tid + 384) >> 3 };
    const int vC = tid & 7;

    auto stage_tile = [&](int kt) {
        const uint32_t sb = smb + (uint32_t)(kt & 3) * STG_BYTES;
        const int kb = kt * 64;
        CP_ASYNC16(sb + kR0 * 80 + kC0 * 16, Kp4 + (size_t)(kb + kR0) * 4 + kC0);
        CP_ASYNC16(sb + kR1 * 80 + kC0 * 16, Kp4 + (size_t)(kb + kR1) * 4 + kC0);
        const uint32_t vb = sb + 5120;
        #pragma unroll
        for (int i = 0; i < 4; i++)
            CP_ASYNC16(vb + vR[i] * 144 + vC * 16, Vp4 + (size_t)vR[i] * 392 + kt * 8 + vC);
    };

    float o[8][4] = {};
    float rs0 = 0.f, rs1 = 0.f;
    float m0 = -3.0e38f, m1 = -3.0e38f;

    // ---- pipeline prologue: 3 stages in flight ----
    stage_tile(0); CP_COMMIT();
    stage_tile(1); CP_COMMIT();
    stage_tile(2); CP_COMMIT();

    for (int kt = 0; kt < NT64; kt++) {
        CP_WAIT2();
        __syncthreads();
        if (kt + 3 < NT64) stage_tile(kt + 3);
        CP_COMMIT();

        const uint2*    sK = (const uint2*)(smem + (kt & 3) * STG_BYTES);          // stride 10
        const uint32_t* sV = (const uint32_t*)(smem + (kt & 3) * STG_BYTES + 5120);// stride 36

        // ---- S = Q K^T : 8 key-groups x 3 split MMAs ----
        float s[8][4] = {};
        #pragma unroll
        for (int j = 0; j < 8; j++) {
            const uint2 b0 = sK[(8 * j + g) * 10 + t];
            const uint2 b1 = sK[(8 * j + g) * 10 + t + 4];
            mma16816h(s[j], Qhi, b0.x, b1.x);
            mma16816h(s[j], Qhi, b0.y, b1.y);
            mma16816h(s[j], Qlo, b0.x, b1.x);
        }

        // ---- online max (ballot-gated rescale) ----
        float mt0 = s[0][0], mt1 = s[0][2];
        #pragma unroll
        for (int j = 0; j < 8; j++) {
            mt0 = fmaxf(mt0, fmaxf(s[j][0], s[j][1]));
            mt1 = fmaxf(mt1, fmaxf(s[j][2], s[j][3]));
        }
        mt0 = fmaxf(mt0, __shfl_xor_sync(0xffffffffu, mt0, 1));
        mt0 = fmaxf(mt0, __shfl_xor_sync(0xffffffffu, mt0, 2));
        mt1 = fmaxf(mt1, __shfl_xor_sync(0xffffffffu, mt1, 1));
        mt1 = fmaxf(mt1, __shfl_xor_sync(0xffffffffu, mt1, 2));
        const bool ch = (mt0 > m0) | (mt1 > m1);
        if (__ballot_sync(0xffffffffu, ch) != 0u) {
            const float mn0 = fmaxf(m0, mt0), mn1 = fmaxf(m1, mt1);
            const float c0 = __expf(m0 - mn0), c1 = __expf(m1 - mn1);
            m0 = mn0; m1 = mn1;
            rs0 *= c0; rs1 *= c1;
            #pragma unroll
            for (int j = 0; j < 8; j++) {
                o[j][0] *= c0; o[j][1] *= c0;
                o[j][2] *= c1; o[j][3] *= c1;
            }
        }

        // ---- P = exp(S - m), rowsum ----
        #pragma unroll
        for (int j = 0; j < 8; j++) {
            s[j][0] = __expf(s[j][0] - m0);
            s[j][1] = __expf(s[j][1] - m0);
            s[j][2] = __expf(s[j][2] - m1);
            s[j][3] = __expf(s[j][3] - m1);
            rs0 += s[j][0] + s[j][1];
            rs1 += s[j][2] + s[j][3];
        }

        // ---- O += P V (paired-V: one LDS.64 per operand pair) ----
        #pragma unroll
        for (int ss = 0; ss < 4; ss++) {
            uint32_t ph[4];
            ph[0] = packh(s[2*ss  ][0], s[2*ss  ][1]);
            ph[1] = packh(s[2*ss  ][2], s[2*ss  ][3]);
            ph[2] = packh(s[2*ss+1][0], s[2*ss+1][1]);
            ph[3] = packh(s[2*ss+1][2], s[2*ss+1][3]);
            const int col2 = 8 * ss + 2 * t;
            #pragma unroll
            for (int j = 0; j < 8; j++) {
                const uint2 vv = *(const uint2*)&sV[(8 * j + g) * 36 + col2];
                mma16816h(o[j], ph, vv.x, vv.y);
            }
        }
    }

    rs0 += __shfl_xor_sync(0xffffffffu, rs0, 1);
    rs0 += __shfl_xor_sync(0xffffffffu, rs0, 2);
    rs1 += __shfl_xor_sync(0xffffffffu, rs1, 1);
    rs1 += __shfl_xor_sync(0xffffffffu, rs1, 2);
    const float inv0 = 1.f / rs0;
    const float inv1 = 1.f / rs1;

    // ---- write relu(O) split pairs: dpair = 4j+t (d = 8j+2t, +1) ----
    uint32_t hi, lo;
    uint2* ob  = g_Oph + ((size_t)bh * NPIX + row0) * 32;
    uint2* ob1 = ob + 8 * 32;
    #pragma unroll
    for (int j = 0; j < 8; j++) {
        split2h(fmaxf(o[j][0] * inv0, 0.f), fmaxf(o[j][1] * inv0, 0.f), hi, lo);
        ob[4 * j + t] = make_uint2(hi, lo);
        split2h(fmaxf(o[j][2] * inv1, 0.f), fmaxf(o[j][3] * inv1, 0.f), hi, lo);
        ob1[4 * j + t] = make_uint2(hi, lo);
    }
}

// ---------------------------------------------------------------------------
// K3: projection via MMA. grid (25, 3, 2), block 256 (8 warps).
// Block: 128 pixels x 128 oc, K=512 in 32 steps. A = relu(O) pairs (g_Oph).
// ---------------------------------------------------------------------------
__global__ __launch_bounds__(256, 2) void proj_mma(float* __restrict__ out)
{
    __shared__ uint2 sW[128][9];

    const int b = blockIdx.z;
    const int oc0 = blockIdx.y * 128;
    const int pix0 = blockIdx.x * 128;
    const int tid = threadIdx.x;
    const int w = tid >> 5, lane = tid & 31;
    const int g = lane >> 2, t = lane & 3;
    const int row0 = pix0 + 16 * w + g;
    const int r0c = min(row0, NPIX - 1), r1c = min(row0 + 8, NPIX - 1);

    float acc[16][4] = {};

    for (int s = 0; s < 32; s++) {
        __syncthreads();
        {
            const int i0 = tid * 4;
            #pragma unroll
            for (int i = 0; i < 4; i++) {
                const int idx = i0 + i, rr = idx >> 3, pp = idx & 7;
                sW[rr][pp] = g_Wpp[(size_t)(oc0 + rr) * DHP + 8 * s + pp];
            }
        }
        __syncthreads();

        const int head = s >> 2, dp = 8 * (s & 3) + t;
        const uint2* Ob = g_Oph + ((size_t)(b * HEADS + head) * NPIX) * 32;
        const uint2 a0 = Ob[(size_t)r0c * 32 + dp];
        const uint2 a1 = Ob[(size_t)r1c * 32 + dp];
        const uint2 a2 = Ob[(size_t)r0c * 32 + dp + 4];
        const uint2 a3 = Ob[(size_t)r1c * 32 + dp + 4];
        const uint32_t Ah[4] = {a0.x, a1.x, a2.x, a3.x};
        const uint32_t Al[4] = {a0.y, a1.y, a2.y, a3.y};

        #pragma unroll
        for (int j = 0; j < 16; j++) {
            const uint2 b0 = sW[8 * j + g][t];
            const uint2 b1 = sW[8 * j + g][t + 4];
            mma16816h(acc[j], Ah, b0.x, b1.x);
            mma16816h(acc[j], Ah, b0.y, b1.y);
            mma16816h(acc[j], Al, b0.x, b1.x);
        }
    }

    #pragma unroll
    for (int j = 0; j < 16; j++) {
        const int oc = oc0 + 8 * j + 2 * t;
        const float s0 = g_shiftP[oc], s1 = g_shiftP[oc + 1];
        float* ob = out + ((size_t)b * OCOUT + oc) * NPIX;
        if (row0 < NPIX) {
            ob[row0] = acc[j][0] + s0;
            ob[NPIX + row0] = acc[j][1] + s1;
        }
        if (row0 + 8 < NPIX) {
            ob[row0 + 8] = acc[j][2] + s0;
            ob[NPIX + row0 + 8] = acc[j][3] + s1;
        }
    }
}

// ---------------------------------------------------------------------------
extern "C" void kernel_launch(void* const* d_in, const int* in_sizes, int n_in,
                              void* d_out, int out_size)
{
    (void)in_sizes; (void)n_in; (void)out_size;
    const float* x   = (const float*)d_in[0];
    const float* wq  = (const float*)d_in[1];
    const float* qg  = (const float*)d_in[2];
    const float* qb  = (const float*)d_in[3];
    const float* qm  = (const float*)d_in[4];
    const float* qv  = (const float*)d_in[5];
    const float* wk  = (const float*)d_in[6];
    const float* kg  = (const float*)d_in[7];
    const float* kb  = (const float*)d_in[8];
    const float* km  = (const float*)d_in[9];
    const float* kvv = (const float*)d_in[10];
    const float* wv  = (const float*)d_in[11];
    const float* vg  = (const float*)d_in[12];
    const float* vb  = (const float*)d_in[13];
    const float* vm  = (const float*)d_in[14];
    const float* vvv = (const float*)d_in[15];
    const float* wp  = (const float*)d_in[16];
    const float* pg  = (const float*)d_in[17];
    const float* pb  = (const float*)d_in[18];
    const float* pm  = (const float*)d_in[19];
    const float* pvv = (const float*)d_in[20];
    float* out = (float*)d_out;

    cudaFuncSetAttribute(attn_mma_kernel, cudaFuncAttributeMaxDynamicSharedMemorySize, ATTN_SMEM);

    prep_x<<<dim3(NT64, 6, BATCH), 256>>>(x);
    prep_w<<<dim3(1152), 256>>>(wq, wk, wv, wp,
                                qg, qb, qm, qv,
                                kg, kb, km, kvv,
                                vg, vb, vm, vvv,
                                pg, pb, pm, pvv);
    qkv_mma<<<dim3(QT128, 6, BATCH), 256>>>();
    attn_mma_kernel<<<dim3(NT64, BH), 128, ATTN_SMEM>>>();
    proj_mma<<<dim3(QT128, 3, BATCH), 256>>>(out);
}

// round 10
// speedup vs baseline: 4.4879x; 1.0223x over previous
#include <cuda_runtime.h>
#include <cuda_fp16.h>
#include <cstdint>

// ---------------------------------------------------------------------------
// EfficientViT attention block — all three GEMMs on tensor cores (mma.sync
// m16n8k16 fp16), fp32-accuracy via hi/lo split operands (3-MMA products).
//   P1: prep_x  : x -> transposed fp16 hi/lo pairs  g_Xp[b][pix][icpair]
//   P2: prep_w  : BN-scale-folded, split weights g_Wall (qkv) / g_Wpp (proj)
//   K1: qkv_mma : Q/K (split, PAIR-PERMUTED, Q pre-scaled by log2e)
//                 + V (transposed, PAIR-PERMUTED fp16)
//   K2: attn    : softmax(QK^T)V in exp2 domain, rowsum via ones-MMA,
//                 3-stage cp.async ring, ballot-gated rescale
//   K3: proj_mma: out = Wp @ relu(O) + shift via MMA
// ---------------------------------------------------------------------------

namespace {
constexpr int BATCH = 2;
constexpr int CIN   = 384;
constexpr int NPIX  = 3136;     // 56*56
constexpr int HEADS = 8;
constexpr int KD    = 16;
constexpr int DV    = 64;
constexpr int DH    = 512;
constexpr int OCOUT = 384;
constexpr int BH    = BATCH * HEADS;
constexpr int NT64  = NPIX / 64;             // 49 key tiles / q tiles of 64
constexpr int QT128 = (NPIX + 127) / 128;    // 25 pixel tiles of 128 (GEMMs)
constexpr int ICP   = CIN / 2;               // 192 ic-pairs
constexpr int DHP   = DH / 2;                // 256 ic-pairs for proj
constexpr float EPSBN = 1e-5f;
constexpr float LOG2E = 1.44269504088896341f;

// attn smem ring: 3 stages x (K 64x80B + V 64x144B) = 3 x 14336 = 43008 B
constexpr int STG_BYTES = 64 * 80 + 64 * 144;   // 14336
constexpr int ATTN_SMEM = 3 * STG_BYTES;        // 43008
constexpr uint32_t ONESH2 = 0x3C003C00u;        // f16x2 {1.0, 1.0}
}

// scratch (static device arrays: allocation-free per harness rules)
__device__ __align__(16) uint2    g_Xp[BATCH * NPIX * ICP];        // x^T split
__device__ __align__(16) uint2    g_Wall[(256 + DH) * ICP];        // 768 rows q,k,v
__device__ __align__(16) uint2    g_Wpp[OCOUT * DHP];              // proj W
__device__            float       g_shiftAll[768];
__device__            float       g_shiftP[OCOUT];
__device__ __align__(16) uint2    g_Qp[BH * NPIX * 8];             // [bh][pix][perm kdpair]{hi,lo}
__device__ __align__(16) uint2    g_Kp[BH * NPIX * 8];
__device__ __align__(16) uint32_t g_Vh[BH * DV * (NPIX / 2)];      // [bh][d][perm keypair] f16x2
__device__ __align__(16) uint2    g_Oph[BH * NPIX * (DV / 2)];     // relu(O) split [bh][pix][dpair]

// split fp32 pair -> f16x2 hi (v0 low half) + f16x2 lo (residuals)
__device__ __forceinline__ void split2h(float v0, float v1, uint32_t& hi, uint32_t& lo) {
    __half h0 = __float2half_rn(v0), h1 = __float2half_rn(v1);
    hi = ((uint32_t)__half_as_ushort(h1) << 16) | (uint32_t)__half_as_ushort(h0);
    float r0 = v0 - __half2float(h0);
    float r1 = v1 - __half2float(h1);
    asm("cvt.rn.f16x2.f32 %0, %1, %2;" : "=r"(lo) : "f"(r1), "f"(r0));
}
__device__ __forceinline__ uint32_t packh(float v0, float v1) {
    uint32_t d; asm("cvt.rn.f16x2.f32 %0, %1, %2;" : "=r"(d) : "f"(v1), "f"(v0)); return d;
}
__device__ __forceinline__ float ex2(float x) {
    float r; asm("ex2.approx.ftz.f32 %0, %1;" : "=f"(r) : "f"(x)); return r;
}
__device__ __forceinline__ uint32_t smem_u32(const void* p) {
    uint32_t a;
    asm("{ .reg .u64 t; cvta.to.shared.u64 t, %1; cvt.u32.u64 %0, t; }" : "=r"(a) : "l"(p));
    return a;
}
#define CP_ASYNC16(dst, src) \
    asm volatile("cp.async.cg.shared.global [%0], [%1], 16;" :: "r"(dst), "l"(src))
#define CP_COMMIT() asm volatile("cp.async.commit_group;" ::: "memory")
#define CP_WAIT1()  asm volatile("cp.async.wait_group 1;"  ::: "memory")

// mma.sync m16n8k16 fp16 -> f32 accum
// A frag: {(g,t),(g+8,t),(g,t+4),(g+8,t+4)} pair-granularity; B: n=g, kpair=t/t+4;
// C: row=g/g+8, col=2t/2t+1.   (empirically validated rounds 5-9)
__device__ __forceinline__ void mma16816h(float* c, const uint32_t* a, uint32_t b0, uint32_t b1) {
    asm volatile("mma.sync.aligned.m16n8k16.row.col.f32.f16.f16.f32 "
        "{%0,%1,%2,%3}, {%4,%5,%6,%7}, {%8,%9}, {%0,%1,%2,%3};"
        : "+f"(c[0]), "+f"(c[1]), "+f"(c[2]), "+f"(c[3])
        : "r"(a[0]), "r"(a[1]), "r"(a[2]), "r"(a[3]), "r"(b0), "r"(b1));
}

// ---------------------------------------------------------------------------
// P1: transpose + split x. grid (49, 6, 2), block 256. 64 pix x 64 ch per blk.
// ---------------------------------------------------------------------------
__global__ __launch_bounds__(256) void prep_x(const float* __restrict__ x)
{
    __shared__ float s[8][66];
    const int pix0 = blockIdx.x * 64;
    const int cc0  = blockIdx.y * 64;
    const int b    = blockIdx.z;
    const int tid  = threadIdx.x;
    const int lr = tid >> 5, lc = (tid & 31) * 2;
    const int pix = tid >> 2, gp = tid & 3;

    for (int cc = cc0; cc < cc0 + 64; cc += 8) {
        float2 v = *(const float2*)(x + ((size_t)b * CIN + cc + lr) * NPIX + pix0 + lc);
        s[lr][lc] = v.x; s[lr][lc + 1] = v.y;
        __syncthreads();
        uint32_t hi, lo;
        split2h(s[2 * gp][pix], s[2 * gp + 1][pix], hi, lo);
        g_Xp[((size_t)b * NPIX + pix0 + pix) * ICP + (cc >> 1) + gp] = make_uint2(hi, lo);
        __syncthreads();
    }
}

// ---------------------------------------------------------------------------
// P2: fold BN scale into weights, split fp16 hi/lo; compute shifts.
// grid 1152, block 256. rows 0..767 -> g_Wall (q,k,v), 768..1151 -> g_Wpp.
// ---------------------------------------------------------------------------
__global__ __launch_bounds__(256) void prep_w(
    const float* __restrict__ wq, const float* __restrict__ wk,
    const float* __restrict__ wv, const float* __restrict__ wp,
    const float* __restrict__ qg, const float* __restrict__ qb, const float* __restrict__ qm, const float* __restrict__ qv,
    const float* __restrict__ kg, const float* __restrict__ kb, const float* __restrict__ km, const float* __restrict__ kvv,
    const float* __restrict__ vg, const float* __restrict__ vb, const float* __restrict__ vm, const float* __restrict__ vvv,
    const float* __restrict__ pg, const float* __restrict__ pb, const float* __restrict__ pm, const float* __restrict__ pvv)
{
    const int r = blockIdx.x, t = threadIdx.x;
    if (r < 768) {
        const float *w, *gg, *bb, *mm, *vx; int rr;
        if (r < 128)      { w = wq; gg = qg; bb = qb; mm = qm; vx = qv;  rr = r; }
        else if (r < 256) { w = wk; gg = kg; bb = kb; mm = km; vx = kvv; rr = r - 128; }
        else              { w = wv; gg = vg; bb = vb; mm = vm; vx = vvv; rr = r - 256; }
        const float sc = gg[rr] * rsqrtf(vx[rr] + EPSBN);
        if (t == 0) g_shiftAll[r] = bb[rr] - mm[rr] * sc;
        if (t < ICP) {
            float2 w2 = *(const float2*)(w + (size_t)rr * CIN + 2 * t);
            uint32_t hi, lo; split2h(w2.x * sc, w2.y * sc, hi, lo);
            g_Wall[(size_t)r * ICP + t] = make_uint2(hi, lo);
        }
    } else {
        const int rp = r - 768;
        const float sc = pg[rp] * rsqrtf(pvv[rp] + EPSBN);
        if (t == 0) g_shiftP[rp] = pb[rp] - pm[rp] * sc;
        float2 w2 = *(const float2*)(wp + (size_t)rp * DH + 2 * t);
        uint32_t hi, lo; split2h(w2.x * sc, w2.y * sc, hi, lo);
        g_Wpp[(size_t)rp * DHP + t] = make_uint2(hi, lo);
    }
}

// ---------------------------------------------------------------------------
// K1: QKV projection via MMA. grid (25, 6, 2), block 256 (8 warps).
// Block: 128 pixels (M) x 128 out-channels (N), K=384 in 24 steps.
// by: 0 -> Q(oc 0-127, scaled by log2e), 1 -> K, 2..5 -> V(oc 256-767).
// ---------------------------------------------------------------------------
__global__ __launch_bounds__(256, 2) void qkv_mma()
{
    __shared__ uint2 sW[128][9];

    const int by  = blockIdx.y, b = blockIdx.z;
    const int oc0 = by * 128;
    const int pix0 = blockIdx.x * 128;
    const int tid = threadIdx.x;
    const int w   = tid >> 5, lane = tid & 31;
    const int g   = lane >> 2, t = lane & 3;
    const int row0 = pix0 + 16 * w + g;
    const int r0c = min(row0, NPIX - 1), r1c = min(row0 + 8, NPIX - 1);

    const uint2* Xb0 = g_Xp + (size_t)b * NPIX * ICP + (size_t)r0c * ICP;
    const uint2* Xb1 = g_Xp + (size_t)b * NPIX * ICP + (size_t)r1c * ICP;

    float acc[16][4] = {};

    for (int s = 0; s < 24; s++) {
        __syncthreads();
        {   // stage 128 oc x 8 pairs of W
            const int i0 = tid * 4;
            #pragma unroll
            for (int i = 0; i < 4; i++) {
                const int idx = i0 + i, rr = idx >> 3, pp = idx & 7;
                sW[rr][pp] = g_Wall[(size_t)(oc0 + rr) * ICP + 8 * s + pp];
            }
        }
        __syncthreads();

        const uint2 a0 = Xb0[8 * s + t];
        const uint2 a1 = Xb1[8 * s + t];
        const uint2 a2 = Xb0[8 * s + t + 4];
        const uint2 a3 = Xb1[8 * s + t + 4];
        const uint32_t Ah[4] = {a0.x, a1.x, a2.x, a3.x};
        const uint32_t Al[4] = {a0.y, a1.y, a2.y, a3.y};

        #pragma unroll
        for (int j = 0; j < 16; j++) {
            const uint2 b0 = sW[8 * j + g][t];
            const uint2 b1 = sW[8 * j + g][t + 4];
            mma16816h(acc[j], Ah, b0.x, b1.x);
            mma16816h(acc[j], Ah, b0.y, b1.y);
            mma16816h(acc[j], Al, b0.x, b1.x);
        }
    }

    if (by < 2) {
        // ---- Q or K: kd-pairs in-lane; PAIR-PERMUTED position so attn's
        // (t, t+4) operands are adjacent: newp = ((kdp&3)<<1)|(kdp>>2).
        // Q additionally pre-scaled by log2e (exp2-domain softmax).
        uint2* QK = (by == 0) ? g_Qp : g_Kp;
        const float qs = (by == 0) ? LOG2E : 1.0f;
        #pragma unroll
        for (int j = 0; j < 16; j++) {
            const int ocl = 8 * j + 2 * t;
            const float s0 = g_shiftAll[oc0 + ocl], s1 = g_shiftAll[oc0 + ocl + 1];
            const int head = ocl >> 4, kdp = (ocl & 15) >> 1;
            const int newp = ((kdp & 3) << 1) | (kdp >> 2);
            uint2* base = QK + ((size_t)(b * HEADS + head) * NPIX) * 8 + newp;
            uint32_t hi, lo;
            if (row0 < NPIX) {
                split2h((acc[j][0] + s0) * qs, (acc[j][1] + s1) * qs, hi, lo);
                base[(size_t)row0 * 8] = make_uint2(hi, lo);
            }
            if (row0 + 8 < NPIX) {
                split2h((acc[j][2] + s0) * qs, (acc[j][3] + s1) * qs, hi, lo);
                base[(size_t)(row0 + 8) * 8] = make_uint2(hi, lo);
            }
        }
    } else {
        // ---- V: pixel-pairs via shfl; PAIR-PERMUTED layout within 32-pair
        // tiles so that attn's PV B-operand (c, c+4) is one LDS.64:
        // newc = (c & 24) | ((c & 3) << 1) | ((c >> 2) & 1)
        #pragma unroll
        for (int j = 0; j < 16; j++) {
            const int ocv = (by - 2) * 128 + 8 * j + 2 * t;
            const float s0 = g_shiftAll[256 + ocv], s1 = g_shiftAll[256 + ocv + 1];
            const int head = ocv >> 6, d = ocv & 63;
            const float v00 = acc[j][0] + s0, v01 = acc[j][1] + s1;
            const float v10 = acc[j][2] + s0, v11 = acc[j][3] + s1;
            const float n00 = __shfl_down_sync(0xffffffffu, v00, 4);
            const float n01 = __shfl_down_sync(0xffffffffu, v01, 4);
            const float n10 = __shfl_down_sync(0xffffffffu, v10, 4);
            const float n11 = __shfl_down_sync(0xffffffffu, v11, 4);
            if (!(g & 1)) {
                uint32_t* vb = g_Vh + ((size_t)(b * HEADS + head) * DV + d) * (NPIX / 2);
                const int pp0 = row0 >> 1, pp1 = (row0 + 8) >> 1;
                const int c0 = pp0 & 31, c1 = pp1 & 31;
                const int q0i = (pp0 & ~31) | (c0 & 24) | ((c0 & 3) << 1) | ((c0 >> 2) & 1);
                const int q1i = (pp1 & ~31) | (c1 & 24) | ((c1 & 3) << 1) | ((c1 >> 2) & 1);
                if (row0 + 1 < NPIX) {
                    vb[q0i] = packh(v00, n00);
                    vb[(NPIX / 2) + q0i] = packh(v01, n01);
                }
                if (row0 + 9 < NPIX) {
                    vb[q1i] = packh(v10, n10);
                    vb[(NPIX / 2) + q1i] = packh(v11, n11);
                }
            }
        }
    }
}

// ---------------------------------------------------------------------------
// K2: attention. grid (49, 16), block 128 (4 warps), q-tile 64 (exact).
// 3-stage cp.async ring, exp2-domain softmax, rowsum via ones-MMA,
// ballot-gated accumulator rescale.
// ---------------------------------------------------------------------------
__global__ __launch_bounds__(128, 4) void attn_mma_kernel()
{
    extern __shared__ __align__(16) unsigned char smem[];

    const int bh  = blockIdx.y;
    const int q0  = blockIdx.x * 64;
    const int tid = threadIdx.x;
    const int lane = tid & 31;
    const int w   = tid >> 5;
    const int g   = lane >> 2, t = lane & 3;
    const int row0 = q0 + w * 16 + g;            // always < NPIX (exact tiling)

    // ---- Q fragments (hi/lo), paired layout: one uint4 per row ----
    const uint2* Qp = g_Qp + (size_t)bh * NPIX * 8;
    const uint4 qA = *(const uint4*)(Qp + (size_t)row0 * 8 + 2 * t);
    const uint4 qB = *(const uint4*)(Qp + (size_t)(row0 + 8) * 8 + 2 * t);
    const uint32_t Qhi[4] = {qA.x, qB.x, qA.z, qB.z};
    const uint32_t Qlo[4] = {qA.y, qB.y, qA.w, qB.w};

    const uint4* Kp4 = (const uint4*)(g_Kp + (size_t)bh * NPIX * 8);      // 4 uint4 per key
    const uint4* Vp4 = (const uint4*)(g_Vh + (size_t)bh * DV * (NPIX/2)); // 392 uint4 per d-row

    const uint32_t smb = smem_u32(smem);
    const int kR0 = tid >> 2,        kC0 = (tid & 3);
    const int kR1 = (tid + 128) >> 2;
    const int vR[4] = { tid >> 3, (tid + 128) >> 3, (tid + 256) >> 3, (tid + 384) >> 3 };
    const int vC = tid & 7;

    auto stage_tile = [&](int kt, int slot) {
        const uint32_t sb = smb + (uint32_t)slot * STG_BYTES;
        const int kb = kt * 64;
        CP_ASYNC16(sb + kR0 * 80 + kC0 * 16, Kp4 + (size_t)(kb + kR0) * 4 + kC0);
        CP_ASYNC16(sb + kR1 * 80 + kC0 * 16, Kp4 + (size_t)(kb + kR1) * 4 + kC0);
        const uint32_t vb = sb + 5120;
        #pragma unroll
        for (int i = 0; i < 4; i++)
            CP_ASYNC16(vb + vR[i] * 144 + vC * 16, Vp4 + (size_t)vR[i] * 392 + kt * 8 + vC);
    };

    float o[8][4] = {};
    float o9[4] = {};                 // rowsum accumulator (P . ones)
    float m0 = -3.0e38f, m1 = -3.0e38f;

    stage_tile(0, 0); CP_COMMIT();
    stage_tile(1, 1); CP_COMMIT();

    int cur = 0, nxt = 2;
    for (int kt = 0; kt < NT64; kt++) {
        CP_WAIT1();
        __syncthreads();
        if (kt + 2 < NT64) stage_tile(kt + 2, nxt);
        CP_COMMIT();

        const unsigned char* stg = smem + cur * STG_BYTES;
        cur = (cur == 2) ? 0 : cur + 1;
        nxt = (nxt == 2) ? 0 : nxt + 1;

        // ---- S = Q K^T : 8 key-groups, 1 LDS.128 + 3 split MMAs each ----
        float s[8][4] = {};
        #pragma unroll
        for (int j = 0; j < 8; j++) {
            const uint4 kv = *(const uint4*)(stg + (8 * j + g) * 80 + t * 16);
            mma16816h(s[j], Qhi, kv.x, kv.z);   // Qh*Kh
            mma16816h(s[j], Qhi, kv.y, kv.w);   // Qh*Kl
            mma16816h(s[j], Qlo, kv.x, kv.z);   // Ql*Kh
        }

        // ---- online max (ballot-gated rescale), log2 domain ----
        float mt0 = s[0][0], mt1 = s[0][2];
        #pragma unroll
        for (int j = 0; j < 8; j++) {
            mt0 = fmaxf(mt0, fmaxf(s[j][0], s[j][1]));
            mt1 = fmaxf(mt1, fmaxf(s[j][2], s[j][3]));
        }
        mt0 = fmaxf(mt0, __shfl_xor_sync(0xffffffffu, mt0, 1));
        mt0 = fmaxf(mt0, __shfl_xor_sync(0xffffffffu, mt0, 2));
        mt1 = fmaxf(mt1, __shfl_xor_sync(0xffffffffu, mt1, 1));
        mt1 = fmaxf(mt1, __shfl_xor_sync(0xffffffffu, mt1, 2));
        const bool chg = (mt0 > m0) | (mt1 > m1);
        if (__ballot_sync(0xffffffffu, chg) != 0u) {
            const float mn0 = fmaxf(m0, mt0), mn1 = fmaxf(m1, mt1);
            const float c0 = ex2(m0 - mn0), c1 = ex2(m1 - mn1);
            m0 = mn0; m1 = mn1;
            o9[0] *= c0; o9[1] *= c0; o9[2] *= c1; o9[3] *= c1;
            #pragma unroll
            for (int j = 0; j < 8; j++) {
                o[j][0] *= c0; o[j][1] *= c0;
                o[j][2] *= c1; o[j][3] *= c1;
            }
        }

        // ---- P = exp2(S - m); pack; PV + rowsum MMAs ----
        const uint32_t* sV = (const uint32_t*)(stg + 5120);   // stride 36
        #pragma unroll
        for (int ss = 0; ss < 4; ss++) {
            uint32_t ph[4];
            ph[0] = packh(ex2(s[2*ss  ][0] - m0), ex2(s[2*ss  ][1] - m0));
            ph[1] = packh(ex2(s[2*ss  ][2] - m1), ex2(s[2*ss  ][3] - m1));
            ph[2] = packh(ex2(s[2*ss+1][0] - m0), ex2(s[2*ss+1][1] - m0));
            ph[3] = packh(ex2(s[2*ss+1][2] - m1), ex2(s[2*ss+1][3] - m1));
            const int col2 = 8 * ss + 2 * t;
            #pragma unroll
            for (int j = 0; j < 8; j++) {
                const uint2 vv = *(const uint2*)&sV[(8 * j + g) * 36 + col2];
                mma16816h(o[j], ph, vv.x, vv.y);
            }
            mma16816h(o9, ph, ONESH2, ONESH2);   // rowsum
        }
    }

    const float inv0 = 1.f / o9[0];
    const float inv1 = 1.f / o9[2];

    // ---- write relu(O) split pairs: dpair = 4j+t (d = 8j+2t, +1) ----
    uint32_t hi, lo;
    uint2* ob  = g_Oph + ((size_t)bh * NPIX + row0) * 32;
    uint2* ob1 = ob + 8 * 32;
    #pragma unroll
    for (int j = 0; j < 8; j++) {
        split2h(fmaxf(o[j][0] * inv0, 0.f), fmaxf(o[j][1] * inv0, 0.f), hi, lo);
        ob[4 * j + t] = make_uint2(hi, lo);
        split2h(fmaxf(o[j][2] * inv1, 0.f), fmaxf(o[j][3] * inv1, 0.f), hi, lo);
        ob1[4 * j + t] = make_uint2(hi, lo);
    }
}

// ---------------------------------------------------------------------------
// K3: projection via MMA. grid (25, 3, 2), block 256 (8 warps).
// Block: 128 pixels x 128 oc, K=512 in 32 steps. A = relu(O) pairs (g_Oph).
// ---------------------------------------------------------------------------
__global__ __launch_bounds__(256, 2) void proj_mma(float* __restrict__ out)
{
    __shared__ uint2 sW[128][9];

    const int b = blockIdx.z;
    const int oc0 = blockIdx.y * 128;
    const int pix0 = blockIdx.x * 128;
    const int tid = threadIdx.x;
    const int w = tid >> 5, lane = tid & 31;
    const int g = lane >> 2, t = lane & 3;
    const int row0 = pix0 + 16 * w + g;
    const int r0c = min(row0, NPIX - 1), r1c = min(row0 + 8, NPIX - 1);

    float acc[16][4] = {};

    for (int s = 0; s < 32; s++) {
        __syncthreads();
        {
            const int i0 = tid * 4;
            #pragma unroll
            for (int i = 0; i < 4; i++) {
                const int idx = i0 + i, rr = idx >> 3, pp = idx & 7;
                sW[rr][pp] = g_Wpp[(size_t)(oc0 + rr) * DHP + 8 * s + pp];
            }
        }
        __syncthreads();

        const int head = s >> 2, dp = 8 * (s & 3) + t;
        const uint2* Ob = g_Oph + ((size_t)(b * HEADS + head) * NPIX) * 32;
        const uint2 a0 = Ob[(size_t)r0c * 32 + dp];
        const uint2 a1 = Ob[(size_t)r1c * 32 + dp];
        const uint2 a2 = Ob[(size_t)r0c * 32 + dp + 4];
        const uint2 a3 = Ob[(size_t)r1c * 32 + dp + 4];
        const uint32_t Ah[4] = {a0.x, a1.x, a2.x, a3.x};
        const uint32_t Al[4] = {a0.y, a1.y, a2.y, a3.y};

        #pragma unroll
        for (int j = 0; j < 16; j++) {
            const uint2 b0 = sW[8 * j + g][t];
            const uint2 b1 = sW[8 * j + g][t + 4];
            mma16816h(acc[j], Ah, b0.x, b1.x);
            mma16816h(acc[j], Ah, b0.y, b1.y);
            mma16816h(acc[j], Al, b0.x, b1.x);
        }
    }

    #pragma unroll
    for (int j = 0; j < 16; j++) {
        const int oc = oc0 + 8 * j + 2 * t;
        const float s0 = g_shiftP[oc], s1 = g_shiftP[oc + 1];
        float* ob = out + ((size_t)b * OCOUT + oc) * NPIX;
        if (row0 < NPIX) {
            ob[row0] = acc[j][0] + s0;
            ob[NPIX + row0] = acc[j][1] + s1;
        }
        if (row0 + 8 < NPIX) {
            ob[row0 + 8] = acc[j][2] + s0;
            ob[NPIX + row0 + 8] = acc[j][3] + s1;
        }
    }
}

// ---------------------------------------------------------------------------
extern "C" void kernel_launch(void* const* d_in, const int* in_sizes, int n_in,
                              void* d_out, int out_size)
{
    (void)in_sizes; (void)n_in; (void)out_size;
    const float* x   = (const float*)d_in[0];
    const float* wq  = (const float*)d_in[1];
    const float* qg  = (const float*)d_in[2];
    const float* qb  = (const float*)d_in[3];
    const float* qm  = (const float*)d_in[4];
    const float* qv  = (const float*)d_in[5];
    const float* wk  = (const float*)d_in[6];
    const float* kg  = (const float*)d_in[7];
    const float* kb  = (const float*)d_in[8];
    const float* km  = (const float*)d_in[9];
    const float* kvv = (const float*)d_in[10];
    const float* wv  = (const float*)d_in[11];
    const float* vg  = (const float*)d_in[12];
    const float* vb  = (const float*)d_in[13];
    const float* vm  = (const float*)d_in[14];
    const float* vvv = (const float*)d_in[15];
    const float* wp  = (const float*)d_in[16];
    const float* pg  = (const float*)d_in[17];
    const float* pb  = (const float*)d_in[18];
    const float* pm  = (const float*)d_in[19];
    const float* pvv = (const float*)d_in[20];
    float* out = (float*)d_out;

    cudaFuncSetAttribute(attn_mma_kernel, cudaFuncAttributeMaxDynamicSharedMemorySize, ATTN_SMEM);

    prep_x<<<dim3(NT64, 6, BATCH), 256>>>(x);
    prep_w<<<dim3(1152), 256>>>(wq, wk, wv, wp,
                                qg, qb, qm, qv,
                                kg, kb, km, kvv,
                                vg, vb, vm, vvv,
                                pg, pb, pm, pvv);
    qkv_mma<<<dim3(QT128, 6, BATCH), 256>>>();
    attn_mma_kernel<<<dim3(NT64, BH), 128, ATTN_SMEM>>>();
    proj_mma<<<dim3(QT128, 3, BATCH), 256>>>(out);
}